// round 9
// baseline (speedup 1.0000x reference)
#include <cuda_runtime.h>
#include <cuda_bf16.h>
#include <cstdint>

using std::uint32_t;

#define B_ 8
#define T_ 1024
#define DIN 512
#define DH 64
#define NH 8
#define BH (B_*NH)
#define TD (T_*DH)

#define NEG_INF (-1e30f)

// Scratch (bf16 hi/lo splits of the fp32-accurate projections):
//  K,Q: [bh][t][d] row-major.  V: TRANSPOSED [bh][d][t].
__device__ __nv_bfloat16 g_Kh [BH * TD];
__device__ __nv_bfloat16 g_Kl [BH * TD];
__device__ __nv_bfloat16 g_Qh [BH * TD];
__device__ __nv_bfloat16 g_Ql [BH * TD];
__device__ __nv_bfloat16 g_Vth[BH * TD];
__device__ __nv_bfloat16 g_Vtl[BH * TD];

__device__ __forceinline__ uint32_t fbits(float x) { return __float_as_uint(x); }

__device__ __forceinline__ void bf_split(float x, __nv_bfloat16& h, __nv_bfloat16& l)
{
    h = __float2bfloat16(x);
    l = __float2bfloat16(x - __bfloat162float(h));
}
__device__ __forceinline__ uint32_t pack_bf2(__nv_bfloat16 a, __nv_bfloat16 b)
{
    __nv_bfloat162 t; t.x = a; t.y = b;
    return *reinterpret_cast<uint32_t*>(&t);
}
// split float pair directly into packed hi / packed lo
__device__ __forceinline__ void split_pack(float x, float y, uint32_t& ph, uint32_t& pl)
{
    __nv_bfloat16 hx, lx, hy, ly;
    bf_split(x, hx, lx);
    bf_split(y, hy, ly);
    ph = pack_bf2(hx, hy);
    pl = pack_bf2(lx, ly);
}

__device__ __forceinline__ void mma_tf32(float4& d,
    uint32_t a0, uint32_t a1, uint32_t a2, uint32_t a3,
    uint32_t b0, uint32_t b1)
{
    asm volatile(
        "mma.sync.aligned.m16n8k8.row.col.f32.tf32.tf32.f32 "
        "{%0,%1,%2,%3}, {%4,%5,%6,%7}, {%8,%9}, {%0,%1,%2,%3};\n"
        : "+f"(d.x), "+f"(d.y), "+f"(d.z), "+f"(d.w)
        : "r"(a0), "r"(a1), "r"(a2), "r"(a3), "r"(b0), "r"(b1));
}

__device__ __forceinline__ void mma_bf16(float4& d,
    uint32_t a0, uint32_t a1, uint32_t a2, uint32_t a3,
    uint32_t b0, uint32_t b1)
{
    asm volatile(
        "mma.sync.aligned.m16n8k16.row.col.f32.bf16.bf16.f32 "
        "{%0,%1,%2,%3}, {%4,%5,%6,%7}, {%8,%9}, {%0,%1,%2,%3};\n"
        : "+f"(d.x), "+f"(d.y), "+f"(d.z), "+f"(d.w)
        : "r"(a0), "r"(a1), "r"(a2), "r"(a3), "r"(b0), "r"(b1));
}

// ---------------------------------------------------------------------------
// Kernel 1a: K/Q projection, 1x tf32 (accuracy proven; softmax-damped path).
// CTA 128x64, BK=16, LDG-prefetch pipeline. Epilogue emits bf16 hi/lo.
// ---------------------------------------------------------------------------
#define AS 136
#define BSS 72

template<int WHICH>   // 0 = K, 1 = Q
__global__ __launch_bounds__(256) void proj_kernel(
    const float* __restrict__ X, const float* __restrict__ W)
{
    __shared__ float As_[16 * AS];
    __shared__ float Bs_[16 * BSS];

    const int tid  = threadIdx.x;
    const int lane = tid & 31;
    const int w    = tid >> 5;
    const int gid  = lane >> 2;
    const int tig  = lane & 3;
    const int wm   = w & 3;
    const int wn   = w >> 2;
    const int m0   = blockIdx.y * 128;
    const int n0   = blockIdx.x * 64;

    const int arow0 = tid >> 2;
    const int akc   = (tid & 3) * 4;
    const int brow  = tid >> 4;
    const int bcol  = (tid & 15) * 4;

    float4 pa0, pa1, pb;
    auto ldg_tile = [&](int k0) {
        pa0 = *(const float4*)(X + (size_t)(m0 + arow0)      * DIN + k0 + akc);
        pa1 = *(const float4*)(X + (size_t)(m0 + arow0 + 64) * DIN + k0 + akc);
        pb  = *(const float4*)(W + (size_t)(k0 + brow) * 512 + n0 + bcol);
    };
    auto sts_tile = [&]() {
        As_[(akc + 0) * AS + arow0] = pa0.x;
        As_[(akc + 1) * AS + arow0] = pa0.y;
        As_[(akc + 2) * AS + arow0] = pa0.z;
        As_[(akc + 3) * AS + arow0] = pa0.w;
        As_[(akc + 0) * AS + arow0 + 64] = pa1.x;
        As_[(akc + 1) * AS + arow0 + 64] = pa1.y;
        As_[(akc + 2) * AS + arow0 + 64] = pa1.z;
        As_[(akc + 3) * AS + arow0 + 64] = pa1.w;
        *(float4*)&Bs_[brow * BSS + bcol] = pb;
    };

    float4 acc[2][4];
#pragma unroll
    for (int mt = 0; mt < 2; mt++)
#pragma unroll
        for (int nt = 0; nt < 4; nt++) acc[mt][nt] = make_float4(0.f,0.f,0.f,0.f);

    ldg_tile(0);
    sts_tile();
    __syncthreads();

#pragma unroll 1
    for (int s = 0; s < 32; s++) {
        const bool has_next = (s + 1 < 32);
        if (has_next) ldg_tile((s + 1) * 16);

#pragma unroll
        for (int ks = 0; ks < 2; ks++) {
            int kb = ks * 8;
            uint32_t a[2][4];
#pragma unroll
            for (int mt = 0; mt < 2; mt++) {
                int m = wm * 32 + mt * 16;
                a[mt][0] = fbits(As_[(kb + tig)     * AS + m + gid]);
                a[mt][1] = fbits(As_[(kb + tig)     * AS + m + gid + 8]);
                a[mt][2] = fbits(As_[(kb + tig + 4) * AS + m + gid]);
                a[mt][3] = fbits(As_[(kb + tig + 4) * AS + m + gid + 8]);
            }
#pragma unroll
            for (int nt = 0; nt < 4; nt++) {
                int n = wn * 32 + nt * 8;
                uint32_t b0 = fbits(Bs_[(kb + tig)     * BSS + n + gid]);
                uint32_t b1 = fbits(Bs_[(kb + tig + 4) * BSS + n + gid]);
#pragma unroll
                for (int mt = 0; mt < 2; mt++)
                    mma_tf32(acc[mt][nt], a[mt][0], a[mt][1], a[mt][2], a[mt][3], b0, b1);
            }
        }

        __syncthreads();
        if (has_next) {
            sts_tile();
            __syncthreads();
        }
    }

    // Epilogue: stage 32 rows, then bf16 hi/lo to [bh][t][d]
    float* stage = As_;
    const int bb    = m0 >> 10;
    const int tbase = m0 & 1023;
#pragma unroll 1
    for (int pass = 0; pass < 4; pass++) {
        __syncthreads();
        if (wm == pass) {
#pragma unroll
            for (int mt = 0; mt < 2; mt++) {
#pragma unroll
                for (int nt = 0; nt < 4; nt++) {
                    int rl = mt * 16 + gid;
                    int cl = wn * 32 + nt * 8 + tig * 2;
                    float4 v = acc[mt][nt];
                    *(float2*)&stage[rl * 68 + cl]       = make_float2(v.x, v.y);
                    *(float2*)&stage[(rl + 8) * 68 + cl] = make_float2(v.z, v.w);
                }
            }
        }
        __syncthreads();
        int tp = tbase + pass * 32;
        {
            int t = tid & 31;
            int h = (tid >> 5) & 7;
            uint32_t ph[4], pl[4];
#pragma unroll
            for (int j = 0; j < 4; j++)
                split_pack(stage[t * 68 + (2*j) * 8 + h],
                           stage[t * 68 + (2*j+1) * 8 + h], ph[j], pl[j]);
            size_t off = (size_t)(bb * NH + h) * TD + (size_t)(tp + t) * 64 + (n0 >> 3);
            if (WHICH == 0) {
                *(uint4*)(g_Kh + off) = *(uint4*)ph;
                *(uint4*)(g_Kl + off) = *(uint4*)pl;
            } else {
                *(uint4*)(g_Qh + off) = *(uint4*)ph;
                *(uint4*)(g_Ql + off) = *(uint4*)pl;
            }
        }
    }
}

// ---------------------------------------------------------------------------
// Kernel 1b: V projection, 3xBF16 m16n8k16 (half the MMA instructions of
// 3xTF32). Padded stride-12-u32 smem tiles (bank-conflict-free frags).
// Epilogue writes transposed bf16 hi/lo [bh][d][t].
// ---------------------------------------------------------------------------
#define VAS 12   // A row stride in u32 (24 bf16)
#define VBS 12   // B row stride in u32
// smem bytes: Ah 128*48=6144, Al 6144, Bh 64*48=3072, Bl 3072 -> 18432
#define VSM_AH 0
#define VSM_AL 6144
#define VSM_BH 12288
#define VSM_BL 15360

__global__ __launch_bounds__(256) void projv_kernel(
    const float* __restrict__ X, const float* __restrict__ W)
{
    __shared__ __align__(16) char vsm[18432];
    uint32_t* Ah32 = (uint32_t*)(vsm + VSM_AH);
    uint32_t* Al32 = (uint32_t*)(vsm + VSM_AL);
    uint32_t* Bh32 = (uint32_t*)(vsm + VSM_BH);
    uint32_t* Bl32 = (uint32_t*)(vsm + VSM_BL);
    __nv_bfloat16* Bh16 = (__nv_bfloat16*)(vsm + VSM_BH);
    __nv_bfloat16* Bl16 = (__nv_bfloat16*)(vsm + VSM_BL);

    const int tid  = threadIdx.x;
    const int lane = tid & 31;
    const int w    = tid >> 5;
    const int gid  = lane >> 2;
    const int tig  = lane & 3;
    const int wm   = w & 3;
    const int wn   = w >> 2;
    const int m0   = blockIdx.y * 128;
    const int n0   = blockIdx.x * 64;

    const int arow0 = tid >> 2;
    const int akc   = (tid & 3) * 4;      // k base (0,4,8,12)
    const int brow  = tid >> 4;           // k row
    const int bcol  = (tid & 15) * 4;     // n base

    float4 pa0, pa1, pb;
    auto ldg_tile = [&](int k0) {
        pa0 = *(const float4*)(X + (size_t)(m0 + arow0)      * DIN + k0 + akc);
        pa1 = *(const float4*)(X + (size_t)(m0 + arow0 + 64) * DIN + k0 + akc);
        pb  = *(const float4*)(W + (size_t)(k0 + brow) * 512 + n0 + bcol);
    };
    auto sts_tile = [&]() {
        uint32_t h0, l0, h1, l1;
        split_pack(pa0.x, pa0.y, h0, l0);
        split_pack(pa0.z, pa0.w, h1, l1);
        Ah32[arow0 * VAS + (akc >> 1)]     = h0;
        Ah32[arow0 * VAS + (akc >> 1) + 1] = h1;
        Al32[arow0 * VAS + (akc >> 1)]     = l0;
        Al32[arow0 * VAS + (akc >> 1) + 1] = l1;
        split_pack(pa1.x, pa1.y, h0, l0);
        split_pack(pa1.z, pa1.w, h1, l1);
        Ah32[(arow0 + 64) * VAS + (akc >> 1)]     = h0;
        Ah32[(arow0 + 64) * VAS + (akc >> 1) + 1] = h1;
        Al32[(arow0 + 64) * VAS + (akc >> 1)]     = l0;
        Al32[(arow0 + 64) * VAS + (akc >> 1) + 1] = l1;
        float vv[4] = {pb.x, pb.y, pb.z, pb.w};
#pragma unroll
        for (int j = 0; j < 4; j++) {
            __nv_bfloat16 h, l;
            bf_split(vv[j], h, l);
            Bh16[(bcol + j) * (VBS * 2) + brow] = h;
            Bl16[(bcol + j) * (VBS * 2) + brow] = l;
        }
    };

    float4 acc[2][4];
#pragma unroll
    for (int mt = 0; mt < 2; mt++)
#pragma unroll
        for (int nt = 0; nt < 4; nt++) acc[mt][nt] = make_float4(0.f,0.f,0.f,0.f);

    ldg_tile(0);
    sts_tile();
    __syncthreads();

#pragma unroll 1
    for (int s = 0; s < 32; s++) {
        const bool has_next = (s + 1 < 32);
        if (has_next) ldg_tile((s + 1) * 16);

        uint32_t ah[2][4], al[2][4];
#pragma unroll
        for (int mt = 0; mt < 2; mt++) {
            int m = wm * 32 + mt * 16 + gid;
            ah[mt][0] = Ah32[m * VAS + tig];
            ah[mt][1] = Ah32[(m + 8) * VAS + tig];
            ah[mt][2] = Ah32[m * VAS + tig + 4];
            ah[mt][3] = Ah32[(m + 8) * VAS + tig + 4];
            al[mt][0] = Al32[m * VAS + tig];
            al[mt][1] = Al32[(m + 8) * VAS + tig];
            al[mt][2] = Al32[m * VAS + tig + 4];
            al[mt][3] = Al32[(m + 8) * VAS + tig + 4];
        }
#pragma unroll
        for (int nt = 0; nt < 4; nt++) {
            int n = wn * 32 + nt * 8 + gid;
            uint32_t b0h = Bh32[n * VBS + tig];
            uint32_t b1h = Bh32[n * VBS + tig + 4];
            uint32_t b0l = Bl32[n * VBS + tig];
            uint32_t b1l = Bl32[n * VBS + tig + 4];
#pragma unroll
            for (int mt = 0; mt < 2; mt++) {
                mma_bf16(acc[mt][nt], ah[mt][0], ah[mt][1], ah[mt][2], ah[mt][3], b0h, b1h);
                mma_bf16(acc[mt][nt], al[mt][0], al[mt][1], al[mt][2], al[mt][3], b0h, b1h);
                mma_bf16(acc[mt][nt], ah[mt][0], ah[mt][1], ah[mt][2], ah[mt][3], b0l, b1l);
            }
        }

        __syncthreads();
        if (has_next) {
            sts_tile();
            __syncthreads();
        }
    }

    // Epilogue: stage 32 rows, write transposed bf16 hi/lo [bh][d][t]
    float* stage = (float*)vsm;    // 32 x 68 floats = 8704 B, fits
    const int bb    = m0 >> 10;
    const int tbase = m0 & 1023;
#pragma unroll 1
    for (int pass = 0; pass < 4; pass++) {
        __syncthreads();
        if (wm == pass) {
#pragma unroll
            for (int mt = 0; mt < 2; mt++) {
#pragma unroll
                for (int nt = 0; nt < 4; nt++) {
                    int rl = mt * 16 + gid;
                    int cl = wn * 32 + nt * 8 + tig * 2;
                    float4 v = acc[mt][nt];
                    *(float2*)&stage[rl * 68 + cl]       = make_float2(v.x, v.y);
                    *(float2*)&stage[(rl + 8) * 68 + cl] = make_float2(v.z, v.w);
                }
            }
        }
        __syncthreads();
        int tp = tbase + pass * 32;
        {
            int dl = tid & 7;
            int h  = (tid >> 3) & 7;
            int tq = tid >> 6;
            uint32_t ph[4], pl[4];
#pragma unroll
            for (int j = 0; j < 4; j++) {
                int t0 = tq * 8 + 2 * j;
                split_pack(stage[t0 * 68 + dl * 8 + h],
                           stage[(t0 + 1) * 68 + dl * 8 + h], ph[j], pl[j]);
            }
            int d = (n0 >> 3) + dl;
            size_t off = (size_t)(bb * NH + h) * TD + (size_t)d * T_ + tp + tq * 8;
            *(uint4*)(g_Vth + off) = *(uint4*)ph;
            *(uint4*)(g_Vtl + off) = *(uint4*)pl;
        }
    }
}

// ---------------------------------------------------------------------------
// Kernel 2: flash attention, bf16 m16n8k16, 3xBF16 splitting.
// P never touches smem: S C-fragments repack directly into PV A-fragments.
// ---------------------------------------------------------------------------
#define KSTR 72   // bf16 stride (36 u32)
#define ATTN_SMEM_BYTES (4*64*KSTR*2 + 64*4)   // 37120

__global__ __launch_bounds__(256, 2) void attn_kernel(
    const int* __restrict__ key_seq, float* __restrict__ out)
{
    extern __shared__ char asmem[];
    __nv_bfloat16* Ksh = (__nv_bfloat16*)asmem;
    __nv_bfloat16* Ksl = Ksh + 64 * KSTR;
    __nv_bfloat16* Vsh = Ksl + 64 * KSTR;      // transposed [d][t]
    __nv_bfloat16* Vsl = Vsh + 64 * KSTR;
    float* sbias = (float*)(Vsl + 64 * KSTR);

    uint32_t* K32h = (uint32_t*)Ksh;
    uint32_t* K32l = (uint32_t*)Ksl;
    uint32_t* V32h = (uint32_t*)Vsh;
    uint32_t* V32l = (uint32_t*)Vsl;

    const int tid  = threadIdx.x;
    const int lane = tid & 31;
    const int w    = tid >> 5;
    const int gid  = lane >> 2;
    const int tig  = lane & 3;
    const int bh   = blockIdx.y;
    const int b    = bh >> 3;
    const int h    = bh & 7;
    const size_t base = (size_t)bh * TD;

    const __nv_bfloat16* gQh = g_Qh + base;
    const __nv_bfloat16* gQl = g_Ql + base;
    const __nv_bfloat16* gKh = g_Kh + base;
    const __nv_bfloat16* gKl = g_Kl + base;
    const __nv_bfloat16* gVh = g_Vth + base;
    const __nv_bfloat16* gVl = g_Vtl + base;
    const int* ksq = key_seq + b * T_;

#pragma unroll 1
    for (int pi = 0; pi < 2; pi++) {
        const int blk = pi ? (7 - blockIdx.x) : blockIdx.x;
        const int q0  = blk * 128;
        const int qlo = q0 + w * 16 + gid;
        const int qhi = qlo + 8;

        uint32_t qh[4][4], ql[4][4];
#pragma unroll
        for (int kt = 0; kt < 4; kt++) {
            const __nv_bfloat16* rlo = gQh + (size_t)qlo * 64 + kt * 16;
            const __nv_bfloat16* rhi = gQh + (size_t)qhi * 64 + kt * 16;
            qh[kt][0] = *(const uint32_t*)(rlo + tig * 2);
            qh[kt][1] = *(const uint32_t*)(rhi + tig * 2);
            qh[kt][2] = *(const uint32_t*)(rlo + 8 + tig * 2);
            qh[kt][3] = *(const uint32_t*)(rhi + 8 + tig * 2);
            const __nv_bfloat16* slo = gQl + (size_t)qlo * 64 + kt * 16;
            const __nv_bfloat16* shi = gQl + (size_t)qhi * 64 + kt * 16;
            ql[kt][0] = *(const uint32_t*)(slo + tig * 2);
            ql[kt][1] = *(const uint32_t*)(shi + tig * 2);
            ql[kt][2] = *(const uint32_t*)(slo + 8 + tig * 2);
            ql[kt][3] = *(const uint32_t*)(shi + 8 + tig * 2);
        }

        float4 acc[8];
#pragma unroll
        for (int nt = 0; nt < 8; nt++) acc[nt] = make_float4(0.f,0.f,0.f,0.f);
        float m_lo = NEG_INF, m_hi = NEG_INF, l_lo = 0.f, l_hi = 0.f;

        const int kmax  = q0 + 128;
        const int khi_w = q0 + w * 16 + 16;

        for (int kb = 0; kb < kmax; kb += 64) {
            __syncthreads();
            for (int f = tid; f < 512; f += 256) {
                int key = f >> 3;
                int c   = (f & 7) * 8;
                size_t go = (size_t)(kb + key) * 64 + c;
                *(uint4*)(Ksh + key * KSTR + c) = *(const uint4*)(gKh + go);
                *(uint4*)(Ksl + key * KSTR + c) = *(const uint4*)(gKl + go);
            }
            for (int f = tid; f < 512; f += 256) {
                int d  = f >> 3;
                int tc = (f & 7) * 8;
                size_t go = (size_t)d * T_ + kb + tc;
                *(uint4*)(Vsh + d * KSTR + tc) = *(const uint4*)(gVh + go);
                *(uint4*)(Vsl + d * KSTR + tc) = *(const uint4*)(gVl + go);
            }
            if (tid < 64)
                sbias[tid] = (ksq[kb + tid] < 0) ? NEG_INF : 0.f;
            __syncthreads();

            if (kb >= khi_w) continue;

            // ---- S = Q . K^T (3xBF16) ----
            float4 s[8];
#pragma unroll
            for (int nt = 0; nt < 8; nt++) s[nt] = make_float4(0.f,0.f,0.f,0.f);
#pragma unroll
            for (int kt = 0; kt < 4; kt++) {
#pragma unroll
                for (int nt = 0; nt < 8; nt++) {
                    int idx = (nt * 8 + gid) * 36 + kt * 8 + tig;
                    uint32_t b0h = K32h[idx], b1h = K32h[idx + 4];
                    uint32_t b0l = K32l[idx], b1l = K32l[idx + 4];
                    mma_bf16(s[nt], qh[kt][0], qh[kt][1], qh[kt][2], qh[kt][3], b0h, b1h);
                    mma_bf16(s[nt], ql[kt][0], ql[kt][1], ql[kt][2], ql[kt][3], b0h, b1h);
                    mma_bf16(s[nt], qh[kt][0], qh[kt][1], qh[kt][2], qh[kt][3], b0l, b1l);
                }
            }

            // ---- mask + scale ----
            float mx_lo = NEG_INF, mx_hi = NEG_INF;
#pragma unroll
            for (int nt = 0; nt < 8; nt++) {
                int ki  = kb + nt * 8 + tig * 2;
                float b0f = sbias[nt * 8 + tig * 2];
                float b1f = sbias[nt * 8 + tig * 2 + 1];
                s[nt].x = (ki     > qlo) ? NEG_INF : fmaf(s[nt].x, 0.125f, b0f);
                s[nt].y = (ki + 1 > qlo) ? NEG_INF : fmaf(s[nt].y, 0.125f, b1f);
                s[nt].z = (ki     > qhi) ? NEG_INF : fmaf(s[nt].z, 0.125f, b0f);
                s[nt].w = (ki + 1 > qhi) ? NEG_INF : fmaf(s[nt].w, 0.125f, b1f);
                mx_lo = fmaxf(mx_lo, fmaxf(s[nt].x, s[nt].y));
                mx_hi = fmaxf(mx_hi, fmaxf(s[nt].z, s[nt].w));
            }
            mx_lo = fmaxf(mx_lo, __shfl_xor_sync(0xffffffffu, mx_lo, 1));
            mx_lo = fmaxf(mx_lo, __shfl_xor_sync(0xffffffffu, mx_lo, 2));
            mx_hi = fmaxf(mx_hi, __shfl_xor_sync(0xffffffffu, mx_hi, 1));
            mx_hi = fmaxf(mx_hi, __shfl_xor_sync(0xffffffffu, mx_hi, 2));

            float mn_lo = fmaxf(m_lo, mx_lo);
            float mn_hi = fmaxf(m_hi, mx_hi);
            float al_lo = __expf(m_lo - mn_lo);
            float al_hi = __expf(m_hi - mn_hi);

            float sum_lo = 0.f, sum_hi = 0.f;
#pragma unroll
            for (int nt = 0; nt < 8; nt++) {
                s[nt].x = __expf(s[nt].x - mn_lo);
                s[nt].y = __expf(s[nt].y - mn_lo);
                s[nt].z = __expf(s[nt].z - mn_hi);
                s[nt].w = __expf(s[nt].w - mn_hi);
                sum_lo += s[nt].x + s[nt].y;
                sum_hi += s[nt].z + s[nt].w;
            }
            sum_lo += __shfl_xor_sync(0xffffffffu, sum_lo, 1);
            sum_lo += __shfl_xor_sync(0xffffffffu, sum_lo, 2);
            sum_hi += __shfl_xor_sync(0xffffffffu, sum_hi, 1);
            sum_hi += __shfl_xor_sync(0xffffffffu, sum_hi, 2);

            l_lo = l_lo * al_lo + sum_lo;  m_lo = mn_lo;
            l_hi = l_hi * al_hi + sum_hi;  m_hi = mn_hi;

#pragma unroll
            for (int nt = 0; nt < 8; nt++) {
                acc[nt].x *= al_lo;  acc[nt].y *= al_lo;
                acc[nt].z *= al_hi;  acc[nt].w *= al_hi;
            }

            // ---- P: D-frag -> A-frag repack in registers (no smem) ----
            uint32_t sh[8][2], sl[8][2];
#pragma unroll
            for (int nt = 0; nt < 8; nt++) {
                split_pack(s[nt].x, s[nt].y, sh[nt][0], sl[nt][0]);
                split_pack(s[nt].z, s[nt].w, sh[nt][1], sl[nt][1]);
            }

            // ---- O += P . V (3xBF16, V transposed in smem) ----
#pragma unroll
            for (int kt = 0; kt < 4; kt++) {
                uint32_t pah0 = sh[2*kt][0],   pah1 = sh[2*kt][1];
                uint32_t pah2 = sh[2*kt+1][0], pah3 = sh[2*kt+1][1];
                uint32_t pal0 = sl[2*kt][0],   pal1 = sl[2*kt][1];
                uint32_t pal2 = sl[2*kt+1][0], pal3 = sl[2*kt+1][1];
#pragma unroll
                for (int nt = 0; nt < 8; nt++) {
                    int idx = (nt * 8 + gid) * 36 + kt * 8 + tig;
                    uint32_t b0h = V32h[idx], b1h = V32h[idx + 4];
                    uint32_t b0l = V32l[idx], b1l = V32l[idx + 4];
                    mma_bf16(acc[nt], pah0, pah1, pah2, pah3, b0h, b1h);
                    mma_bf16(acc[nt], pal0, pal1, pal2, pal3, b0h, b1h);
                    mma_bf16(acc[nt], pah0, pah1, pah2, pah3, b0l, b1l);
                }
            }
        }

        float il_lo = 1.f / l_lo;
        float il_hi = 1.f / l_hi;
#pragma unroll
        for (int nt = 0; nt < 8; nt++) {
            int col = h * DH + nt * 8 + tig * 2;
            *(float2*)(out + (size_t)(b * T_ + qlo) * (NH * DH) + col) =
                make_float2(acc[nt].x * il_lo, acc[nt].y * il_lo);
            *(float2*)(out + (size_t)(b * T_ + qhi) * (NH * DH) + col) =
                make_float2(acc[nt].z * il_hi, acc[nt].w * il_hi);
        }
    }
}

// ---------------------------------------------------------------------------
extern "C" void kernel_launch(void* const* d_in, const int* in_sizes, int n_in,
                              void* d_out, int out_size)
{
    const float* keys    = (const float*)d_in[0];
    const float* queries = (const float*)d_in[1];
    const float* values  = (const float*)d_in[2];
    const float* Wk      = (const float*)d_in[3];
    const float* Wq      = (const float*)d_in[4];
    const float* Wv      = (const float*)d_in[5];
    const int*   key_seq = (const int*)d_in[6];
    float* out = (float*)d_out;

    dim3 g1(512 / 64, (B_ * T_) / 128);
    proj_kernel<0><<<g1, 256>>>(keys,    Wk);
    proj_kernel<1><<<g1, 256>>>(queries, Wq);
    projv_kernel <<<g1, 256>>>(values,  Wv);

    cudaFuncSetAttribute(attn_kernel,
                         cudaFuncAttributeMaxDynamicSharedMemorySize, ATTN_SMEM_BYTES);
    dim3 g2(4, BH);
    attn_kernel<<<g2, 256, ATTN_SMEM_BYTES>>>(key_seq, out);
}

// round 10
// speedup vs baseline: 1.2236x; 1.2236x over previous
#include <cuda_runtime.h>
#include <cuda_bf16.h>
#include <cstdint>

using std::uint32_t;

#define B_ 8
#define T_ 1024
#define DIN 512
#define DH 64
#define NH 8
#define BH (B_*NH)
#define TD (T_*DH)

#define NEG_INF (-1e30f)

// Scratch (bf16 hi/lo splits of fp32-accurate projections):
//  K,Q: [bh][t][d].  V: TRANSPOSED [bh][d][t].
__device__ __nv_bfloat16 g_Kh [BH * TD];
__device__ __nv_bfloat16 g_Kl [BH * TD];
__device__ __nv_bfloat16 g_Qh [BH * TD];
__device__ __nv_bfloat16 g_Ql [BH * TD];
__device__ __nv_bfloat16 g_Vth[BH * TD];
__device__ __nv_bfloat16 g_Vtl[BH * TD];

__device__ __forceinline__ uint32_t fbits(float x) { return __float_as_uint(x); }
__device__ __forceinline__ float tf32_hi(float x)
{ return __uint_as_float(__float_as_uint(x) & 0xFFFFE000u); }

__device__ __forceinline__ void split_tf32(float x, uint32_t& hi, uint32_t& lo)
{
    float h = tf32_hi(x);
    hi = __float_as_uint(h);
    lo = __float_as_uint(x - h);
}
__device__ __forceinline__ void bf_split(float x, __nv_bfloat16& h, __nv_bfloat16& l)
{
    h = __float2bfloat16(x);
    l = __float2bfloat16(x - __bfloat162float(h));
}
__device__ __forceinline__ uint32_t pack_bf2(__nv_bfloat16 a, __nv_bfloat16 b)
{
    __nv_bfloat162 t; t.x = a; t.y = b;
    return *reinterpret_cast<uint32_t*>(&t);
}
__device__ __forceinline__ void split_pack(float x, float y, uint32_t& ph, uint32_t& pl)
{
    __nv_bfloat16 hx, lx, hy, ly;
    bf_split(x, hx, lx);
    bf_split(y, hy, ly);
    ph = pack_bf2(hx, hy);
    pl = pack_bf2(lx, ly);
}

__device__ __forceinline__ void mma_tf32(float4& d,
    uint32_t a0, uint32_t a1, uint32_t a2, uint32_t a3,
    uint32_t b0, uint32_t b1)
{
    asm volatile(
        "mma.sync.aligned.m16n8k8.row.col.f32.tf32.tf32.f32 "
        "{%0,%1,%2,%3}, {%4,%5,%6,%7}, {%8,%9}, {%0,%1,%2,%3};\n"
        : "+f"(d.x), "+f"(d.y), "+f"(d.z), "+f"(d.w)
        : "r"(a0), "r"(a1), "r"(a2), "r"(a3), "r"(b0), "r"(b1));
}
__device__ __forceinline__ void mma_bf16(float4& d,
    uint32_t a0, uint32_t a1, uint32_t a2, uint32_t a3,
    uint32_t b0, uint32_t b1)
{
    asm volatile(
        "mma.sync.aligned.m16n8k16.row.col.f32.bf16.bf16.f32 "
        "{%0,%1,%2,%3}, {%4,%5,%6,%7}, {%8,%9}, {%0,%1,%2,%3};\n"
        : "+f"(d.x), "+f"(d.y), "+f"(d.z), "+f"(d.w)
        : "r"(a0), "r"(a1), "r"(a2), "r"(a3), "r"(b0), "r"(b1));
}

// cp.async helpers
__device__ __forceinline__ void cp16(void* dst_smem, const void* src)
{
    uint32_t d = (uint32_t)__cvta_generic_to_shared(dst_smem);
    asm volatile("cp.async.cg.shared.global [%0], [%1], 16;" :: "r"(d), "l"(src));
}
#define CP_COMMIT() asm volatile("cp.async.commit_group;" ::: "memory")
#define CP_WAIT2()  asm volatile("cp.async.wait_group 2;"  ::: "memory")

// ---------------------------------------------------------------------------
// Kernel 1: projection with cp.async 4-stage pipeline.
// CTA 128x64, BK=16, 8 warps (warp tile 32x32).
// SPLIT=false: 1x tf32 (K,Q).  SPLIT=true: 3x tf32 (V).
// A smem [m][AK] f32, B smem [k][BN] f32 per stage (bank-verified frags).
// Epilogue: bf16 hi/lo; K/Q -> [bh][t][d], V -> transposed [bh][d][t].
// ---------------------------------------------------------------------------
#define NS 4
#define AK 20                      // A k-stride (f32): banks 20*gid+tig all-distinct
#define BN 68                      // B n-stride (f32): banks 4*tig+gid all-distinct
#define STG_F (128*AK + 16*BN)     // 3648 floats per stage
#define PJ_SMEM (NS * STG_F * 4)   // 58368 bytes

template<bool SPLIT, int WHICH>
__global__ __launch_bounds__(256) void proj_kernel(
    const float* __restrict__ X, const float* __restrict__ W)
{
    extern __shared__ float psm[];

    const int tid  = threadIdx.x;
    const int lane = tid & 31;
    const int w    = tid >> 5;
    const int gid  = lane >> 2;
    const int tig  = lane & 3;
    const int wm   = w & 3;
    const int wn   = w >> 2;
    const int m0   = blockIdx.y * 128;
    const int n0   = blockIdx.x * 64;

    auto issue = [&](int s) {
        float* buf = psm + (s & 3) * STG_F;
        int k0 = s * 16;
#pragma unroll
        for (int l = 0; l < 2; l++) {
            int c   = tid + l * 256;
            int row = c >> 2;
            int kc  = (c & 3) * 4;
            cp16(buf + row * AK + kc, X + (size_t)(m0 + row) * DIN + k0 + kc);
        }
        {
            int row = tid >> 4;
            int nc  = (tid & 15) * 4;
            cp16(buf + 128 * AK + row * BN + nc,
                 W + (size_t)(k0 + row) * 512 + n0 + nc);
        }
    };

    float4 acc[2][4];
#pragma unroll
    for (int mt = 0; mt < 2; mt++)
#pragma unroll
        for (int nt = 0; nt < 4; nt++) acc[mt][nt] = make_float4(0.f,0.f,0.f,0.f);

    issue(0); CP_COMMIT();
    issue(1); CP_COMMIT();
    issue(2); CP_COMMIT();

#pragma unroll 1
    for (int s = 0; s < 32; s++) {
        CP_WAIT2();              // stage s landed (<=2 groups pending)
        __syncthreads();

        float* Abuf = psm + (s & 3) * STG_F;
        float* Bbuf = Abuf + 128 * AK;
#pragma unroll
        for (int ks = 0; ks < 2; ks++) {
            int kb = ks * 8;
            float af[2][4];
#pragma unroll
            for (int mt = 0; mt < 2; mt++) {
                int m = wm * 32 + mt * 16;
                af[mt][0] = Abuf[(m + gid)     * AK + kb + tig];
                af[mt][1] = Abuf[(m + 8 + gid) * AK + kb + tig];
                af[mt][2] = Abuf[(m + gid)     * AK + kb + tig + 4];
                af[mt][3] = Abuf[(m + 8 + gid) * AK + kb + tig + 4];
            }
            if (!SPLIT) {
#pragma unroll
                for (int nt = 0; nt < 4; nt++) {
                    int n = wn * 32 + nt * 8;
                    uint32_t b0 = fbits(Bbuf[(kb + tig)     * BN + n + gid]);
                    uint32_t b1 = fbits(Bbuf[(kb + tig + 4) * BN + n + gid]);
#pragma unroll
                    for (int mt = 0; mt < 2; mt++)
                        mma_tf32(acc[mt][nt], fbits(af[mt][0]), fbits(af[mt][1]),
                                 fbits(af[mt][2]), fbits(af[mt][3]), b0, b1);
                }
            } else {
                uint32_t ah[2][4], al[2][4];
#pragma unroll
                for (int mt = 0; mt < 2; mt++)
#pragma unroll
                    for (int r = 0; r < 4; r++)
                        split_tf32(af[mt][r], ah[mt][r], al[mt][r]);
#pragma unroll
                for (int nt = 0; nt < 4; nt++) {
                    int n = wn * 32 + nt * 8;
                    uint32_t b0h, b0l, b1h, b1l;
                    split_tf32(Bbuf[(kb + tig)     * BN + n + gid], b0h, b0l);
                    split_tf32(Bbuf[(kb + tig + 4) * BN + n + gid], b1h, b1l);
#pragma unroll
                    for (int mt = 0; mt < 2; mt++) {
                        mma_tf32(acc[mt][nt], ah[mt][0], ah[mt][1], ah[mt][2], ah[mt][3], b0h, b1h);
                        mma_tf32(acc[mt][nt], al[mt][0], al[mt][1], al[mt][2], al[mt][3], b0h, b1h);
                        mma_tf32(acc[mt][nt], ah[mt][0], ah[mt][1], ah[mt][2], ah[mt][3], b0l, b1l);
                    }
                }
            }
        }

        __syncthreads();         // all warps done reading stage s (and earlier)
        if (s + 3 < 32) issue(s + 3);
        CP_COMMIT();             // one group per iteration keeps accounting exact
    }

    // ---- Epilogue: stage 32 rows via smem, emit bf16 hi/lo ----
    float* stage = psm;          // 32x68 floats
    const int bb    = m0 >> 10;
    const int tbase = m0 & 1023;
#pragma unroll 1
    for (int pass = 0; pass < 4; pass++) {
        __syncthreads();
        if (wm == pass) {
#pragma unroll
            for (int mt = 0; mt < 2; mt++) {
#pragma unroll
                for (int nt = 0; nt < 4; nt++) {
                    int rl = mt * 16 + gid;
                    int cl = wn * 32 + nt * 8 + tig * 2;
                    float4 v = acc[mt][nt];
                    *(float2*)&stage[rl * 68 + cl]       = make_float2(v.x, v.y);
                    *(float2*)&stage[(rl + 8) * 68 + cl] = make_float2(v.z, v.w);
                }
            }
        }
        __syncthreads();
        int tp = tbase + pass * 32;
        if (WHICH < 2) {
            int t = tid & 31;
            int h = (tid >> 5) & 7;
            uint32_t ph[4], pl[4];
#pragma unroll
            for (int j = 0; j < 4; j++)
                split_pack(stage[t * 68 + (2*j) * 8 + h],
                           stage[t * 68 + (2*j+1) * 8 + h], ph[j], pl[j]);
            size_t off = (size_t)(bb * NH + h) * TD + (size_t)(tp + t) * 64 + (n0 >> 3);
            if (WHICH == 0) {
                *(uint4*)(g_Kh + off) = *(uint4*)ph;
                *(uint4*)(g_Kl + off) = *(uint4*)pl;
            } else {
                *(uint4*)(g_Qh + off) = *(uint4*)ph;
                *(uint4*)(g_Ql + off) = *(uint4*)pl;
            }
        } else {
            int dl = tid & 7;
            int h  = (tid >> 3) & 7;
            int tq = tid >> 6;
            uint32_t ph[4], pl[4];
#pragma unroll
            for (int j = 0; j < 4; j++) {
                int t0 = tq * 8 + 2 * j;
                split_pack(stage[t0 * 68 + dl * 8 + h],
                           stage[(t0 + 1) * 68 + dl * 8 + h], ph[j], pl[j]);
            }
            int d = (n0 >> 3) + dl;
            size_t off = (size_t)(bb * NH + h) * TD + (size_t)d * T_ + tp + tq * 8;
            *(uint4*)(g_Vth + off) = *(uint4*)ph;
            *(uint4*)(g_Vtl + off) = *(uint4*)pl;
        }
    }
}

// ---------------------------------------------------------------------------
// Kernel 2: flash attention (R8 version — best measured).
// bf16 m16n8k16, 3xBF16 splitting; P via per-warp smem; paired q-blocks.
// ---------------------------------------------------------------------------
#define KSTR 72
#define ATTN_SMEM_BYTES (4*64*KSTR*2 + 2*8*16*KSTR*2 + 64*4)   // 73984

__global__ __launch_bounds__(256, 2) void attn_kernel(
    const int* __restrict__ key_seq, float* __restrict__ out)
{
    extern __shared__ char asmem[];
    __nv_bfloat16* Ksh = (__nv_bfloat16*)asmem;
    __nv_bfloat16* Ksl = Ksh + 64 * KSTR;
    __nv_bfloat16* Vsh = Ksl + 64 * KSTR;      // transposed [d][t]
    __nv_bfloat16* Vsl = Vsh + 64 * KSTR;
    __nv_bfloat16* Ph  = Vsl + 64 * KSTR;
    __nv_bfloat16* Pl  = Ph + 8 * 16 * KSTR;
    float* sbias = (float*)(Pl + 8 * 16 * KSTR);

    uint32_t* K32h = (uint32_t*)Ksh;
    uint32_t* K32l = (uint32_t*)Ksl;
    uint32_t* V32h = (uint32_t*)Vsh;
    uint32_t* V32l = (uint32_t*)Vsl;

    const int tid  = threadIdx.x;
    const int lane = tid & 31;
    const int w    = tid >> 5;
    const int gid  = lane >> 2;
    const int tig  = lane & 3;
    const int bh   = blockIdx.y;
    const int b    = bh >> 3;
    const int h    = bh & 7;
    const size_t base = (size_t)bh * TD;

    const __nv_bfloat16* gQh = g_Qh + base;
    const __nv_bfloat16* gQl = g_Ql + base;
    const __nv_bfloat16* gKh = g_Kh + base;
    const __nv_bfloat16* gKl = g_Kl + base;
    const __nv_bfloat16* gVh = g_Vth + base;
    const __nv_bfloat16* gVl = g_Vtl + base;
    const int* ksq = key_seq + b * T_;

    uint32_t* P32h = (uint32_t*)(Ph + w * 16 * KSTR);
    uint32_t* P32l = (uint32_t*)(Pl + w * 16 * KSTR);

#pragma unroll 1
    for (int pi = 0; pi < 2; pi++) {
        const int blk = pi ? (7 - blockIdx.x) : blockIdx.x;
        const int q0  = blk * 128;
        const int qlo = q0 + w * 16 + gid;
        const int qhi = qlo + 8;

        uint32_t qh[4][4], ql[4][4];
#pragma unroll
        for (int kt = 0; kt < 4; kt++) {
            const __nv_bfloat16* rlo = gQh + (size_t)qlo * 64 + kt * 16;
            const __nv_bfloat16* rhi = gQh + (size_t)qhi * 64 + kt * 16;
            qh[kt][0] = *(const uint32_t*)(rlo + tig * 2);
            qh[kt][1] = *(const uint32_t*)(rhi + tig * 2);
            qh[kt][2] = *(const uint32_t*)(rlo + 8 + tig * 2);
            qh[kt][3] = *(const uint32_t*)(rhi + 8 + tig * 2);
            const __nv_bfloat16* slo = gQl + (size_t)qlo * 64 + kt * 16;
            const __nv_bfloat16* shi = gQl + (size_t)qhi * 64 + kt * 16;
            ql[kt][0] = *(const uint32_t*)(slo + tig * 2);
            ql[kt][1] = *(const uint32_t*)(shi + tig * 2);
            ql[kt][2] = *(const uint32_t*)(slo + 8 + tig * 2);
            ql[kt][3] = *(const uint32_t*)(shi + 8 + tig * 2);
        }

        float4 acc[8];
#pragma unroll
        for (int nt = 0; nt < 8; nt++) acc[nt] = make_float4(0.f,0.f,0.f,0.f);
        float m_lo = NEG_INF, m_hi = NEG_INF, l_lo = 0.f, l_hi = 0.f;

        const int kmax  = q0 + 128;
        const int khi_w = q0 + w * 16 + 16;

        for (int kb = 0; kb < kmax; kb += 64) {
            __syncthreads();
            for (int f = tid; f < 512; f += 256) {
                int key = f >> 3;
                int c   = (f & 7) * 8;
                size_t go = (size_t)(kb + key) * 64 + c;
                *(uint4*)(Ksh + key * KSTR + c) = *(const uint4*)(gKh + go);
                *(uint4*)(Ksl + key * KSTR + c) = *(const uint4*)(gKl + go);
            }
            for (int f = tid; f < 512; f += 256) {
                int d  = f >> 3;
                int tc = (f & 7) * 8;
                size_t go = (size_t)d * T_ + kb + tc;
                *(uint4*)(Vsh + d * KSTR + tc) = *(const uint4*)(gVh + go);
                *(uint4*)(Vsl + d * KSTR + tc) = *(const uint4*)(gVl + go);
            }
            if (tid < 64)
                sbias[tid] = (ksq[kb + tid] < 0) ? NEG_INF : 0.f;
            __syncthreads();

            if (kb >= khi_w) continue;

            float4 s[8];
#pragma unroll
            for (int nt = 0; nt < 8; nt++) s[nt] = make_float4(0.f,0.f,0.f,0.f);
#pragma unroll
            for (int kt = 0; kt < 4; kt++) {
#pragma unroll
                for (int nt = 0; nt < 8; nt++) {
                    int idx = (nt * 8 + gid) * 36 + kt * 8 + tig;
                    uint32_t b0h = K32h[idx], b1h = K32h[idx + 4];
                    uint32_t b0l = K32l[idx], b1l = K32l[idx + 4];
                    mma_bf16(s[nt], qh[kt][0], qh[kt][1], qh[kt][2], qh[kt][3], b0h, b1h);
                    mma_bf16(s[nt], ql[kt][0], ql[kt][1], ql[kt][2], ql[kt][3], b0h, b1h);
                    mma_bf16(s[nt], qh[kt][0], qh[kt][1], qh[kt][2], qh[kt][3], b0l, b1l);
                }
            }

            float mx_lo = NEG_INF, mx_hi = NEG_INF;
#pragma unroll
            for (int nt = 0; nt < 8; nt++) {
                int ki  = kb + nt * 8 + tig * 2;
                float b0f = sbias[nt * 8 + tig * 2];
                float b1f = sbias[nt * 8 + tig * 2 + 1];
                s[nt].x = (ki     > qlo) ? NEG_INF : fmaf(s[nt].x, 0.125f, b0f);
                s[nt].y = (ki + 1 > qlo) ? NEG_INF : fmaf(s[nt].y, 0.125f, b1f);
                s[nt].z = (ki     > qhi) ? NEG_INF : fmaf(s[nt].z, 0.125f, b0f);
                s[nt].w = (ki + 1 > qhi) ? NEG_INF : fmaf(s[nt].w, 0.125f, b1f);
                mx_lo = fmaxf(mx_lo, fmaxf(s[nt].x, s[nt].y));
                mx_hi = fmaxf(mx_hi, fmaxf(s[nt].z, s[nt].w));
            }
            mx_lo = fmaxf(mx_lo, __shfl_xor_sync(0xffffffffu, mx_lo, 1));
            mx_lo = fmaxf(mx_lo, __shfl_xor_sync(0xffffffffu, mx_lo, 2));
            mx_hi = fmaxf(mx_hi, __shfl_xor_sync(0xffffffffu, mx_hi, 1));
            mx_hi = fmaxf(mx_hi, __shfl_xor_sync(0xffffffffu, mx_hi, 2));

            float mn_lo = fmaxf(m_lo, mx_lo);
            float mn_hi = fmaxf(m_hi, mx_hi);
            float al_lo = __expf(m_lo - mn_lo);
            float al_hi = __expf(m_hi - mn_hi);

            float sum_lo = 0.f, sum_hi = 0.f;
#pragma unroll
            for (int nt = 0; nt < 8; nt++) {
                s[nt].x = __expf(s[nt].x - mn_lo);
                s[nt].y = __expf(s[nt].y - mn_lo);
                s[nt].z = __expf(s[nt].z - mn_hi);
                s[nt].w = __expf(s[nt].w - mn_hi);
                sum_lo += s[nt].x + s[nt].y;
                sum_hi += s[nt].z + s[nt].w;
            }
            sum_lo += __shfl_xor_sync(0xffffffffu, sum_lo, 1);
            sum_lo += __shfl_xor_sync(0xffffffffu, sum_lo, 2);
            sum_hi += __shfl_xor_sync(0xffffffffu, sum_hi, 1);
            sum_hi += __shfl_xor_sync(0xffffffffu, sum_hi, 2);

            l_lo = l_lo * al_lo + sum_lo;  m_lo = mn_lo;
            l_hi = l_hi * al_hi + sum_hi;  m_hi = mn_hi;

#pragma unroll
            for (int nt = 0; nt < 8; nt++) {
                acc[nt].x *= al_lo;  acc[nt].y *= al_lo;
                acc[nt].z *= al_hi;  acc[nt].w *= al_hi;
            }

#pragma unroll
            for (int nt = 0; nt < 8; nt++) {
                uint32_t phx, plx, phz, plz;
                split_pack(s[nt].x, s[nt].y, phx, plx);
                split_pack(s[nt].z, s[nt].w, phz, plz);
                int c = nt * 4 + tig;
                P32h[gid * 36 + c]       = phx;
                P32l[gid * 36 + c]       = plx;
                P32h[(gid + 8) * 36 + c] = phz;
                P32l[(gid + 8) * 36 + c] = plz;
            }
            __syncwarp();

#pragma unroll
            for (int kt = 0; kt < 4; kt++) {
                uint32_t pah[4], pal[4];
                pah[0] = P32h[gid * 36 + kt * 8 + tig];
                pah[1] = P32h[(gid + 8) * 36 + kt * 8 + tig];
                pah[2] = P32h[gid * 36 + kt * 8 + tig + 4];
                pah[3] = P32h[(gid + 8) * 36 + kt * 8 + tig + 4];
                pal[0] = P32l[gid * 36 + kt * 8 + tig];
                pal[1] = P32l[(gid + 8) * 36 + kt * 8 + tig];
                pal[2] = P32l[gid * 36 + kt * 8 + tig + 4];
                pal[3] = P32l[(gid + 8) * 36 + kt * 8 + tig + 4];
#pragma unroll
                for (int nt = 0; nt < 8; nt++) {
                    int idx = (nt * 8 + gid) * 36 + kt * 8 + tig;
                    uint32_t b0h = V32h[idx], b1h = V32h[idx + 4];
                    uint32_t b0l = V32l[idx], b1l = V32l[idx + 4];
                    mma_bf16(acc[nt], pah[0], pah[1], pah[2], pah[3], b0h, b1h);
                    mma_bf16(acc[nt], pal[0], pal[1], pal[2], pal[3], b0h, b1h);
                    mma_bf16(acc[nt], pah[0], pah[1], pah[2], pah[3], b0l, b1l);
                }
            }
        }

        float il_lo = 1.f / l_lo;
        float il_hi = 1.f / l_hi;
#pragma unroll
        for (int nt = 0; nt < 8; nt++) {
            int col = h * DH + nt * 8 + tig * 2;
            *(float2*)(out + (size_t)(b * T_ + qlo) * (NH * DH) + col) =
                make_float2(acc[nt].x * il_lo, acc[nt].y * il_lo);
            *(float2*)(out + (size_t)(b * T_ + qhi) * (NH * DH) + col) =
                make_float2(acc[nt].z * il_hi, acc[nt].w * il_hi);
        }
    }
}

// ---------------------------------------------------------------------------
extern "C" void kernel_launch(void* const* d_in, const int* in_sizes, int n_in,
                              void* d_out, int out_size)
{
    const float* keys    = (const float*)d_in[0];
    const float* queries = (const float*)d_in[1];
    const float* values  = (const float*)d_in[2];
    const float* Wk      = (const float*)d_in[3];
    const float* Wq      = (const float*)d_in[4];
    const float* Wv      = (const float*)d_in[5];
    const int*   key_seq = (const int*)d_in[6];
    float* out = (float*)d_out;

    cudaFuncSetAttribute(proj_kernel<false, 0>,
                         cudaFuncAttributeMaxDynamicSharedMemorySize, PJ_SMEM);
    cudaFuncSetAttribute(proj_kernel<false, 1>,
                         cudaFuncAttributeMaxDynamicSharedMemorySize, PJ_SMEM);
    cudaFuncSetAttribute(proj_kernel<true, 2>,
                         cudaFuncAttributeMaxDynamicSharedMemorySize, PJ_SMEM);

    dim3 g1(512 / 64, (B_ * T_) / 128);
    proj_kernel<false, 0><<<g1, 256, PJ_SMEM>>>(keys,    Wk);
    proj_kernel<false, 1><<<g1, 256, PJ_SMEM>>>(queries, Wq);
    proj_kernel<true,  2><<<g1, 256, PJ_SMEM>>>(values,  Wv);

    cudaFuncSetAttribute(attn_kernel,
                         cudaFuncAttributeMaxDynamicSharedMemorySize, ATTN_SMEM_BYTES);
    dim3 g2(4, BH);
    attn_kernel<<<g2, 256, ATTN_SMEM_BYTES>>>(key_seq, out);
}

// round 11
// speedup vs baseline: 1.3138x; 1.0737x over previous
#include <cuda_runtime.h>
#include <cuda_bf16.h>
#include <cstdint>

using std::uint32_t;

#define B_ 8
#define T_ 1024
#define DIN 512
#define DH 64
#define NH 8
#define BH (B_*NH)
#define TD (T_*DH)

#define NEG_INF (-1e30f)

// Scratch (bf16 hi/lo splits of fp32-accurate projections):
//  K,Q: [bh][t][d].  V: TRANSPOSED [bh][d][t].
__device__ __nv_bfloat16 g_Kh [BH * TD];
__device__ __nv_bfloat16 g_Kl [BH * TD];
__device__ __nv_bfloat16 g_Qh [BH * TD];
__device__ __nv_bfloat16 g_Ql [BH * TD];
__device__ __nv_bfloat16 g_Vth[BH * TD];
__device__ __nv_bfloat16 g_Vtl[BH * TD];

__device__ __forceinline__ uint32_t fbits(float x) { return __float_as_uint(x); }
__device__ __forceinline__ float tf32_hi(float x)
{ return __uint_as_float(__float_as_uint(x) & 0xFFFFE000u); }

__device__ __forceinline__ void split_tf32(float x, uint32_t& hi, uint32_t& lo)
{
    float h = tf32_hi(x);
    hi = __float_as_uint(h);
    lo = __float_as_uint(x - h);
}
__device__ __forceinline__ void bf_split(float x, __nv_bfloat16& h, __nv_bfloat16& l)
{
    h = __float2bfloat16(x);
    l = __float2bfloat16(x - __bfloat162float(h));
}
__device__ __forceinline__ uint32_t pack_bf2(__nv_bfloat16 a, __nv_bfloat16 b)
{
    __nv_bfloat162 t; t.x = a; t.y = b;
    return *reinterpret_cast<uint32_t*>(&t);
}
__device__ __forceinline__ void split_pack(float x, float y, uint32_t& ph, uint32_t& pl)
{
    __nv_bfloat16 hx, lx, hy, ly;
    bf_split(x, hx, lx);
    bf_split(y, hy, ly);
    ph = pack_bf2(hx, hy);
    pl = pack_bf2(lx, ly);
}

__device__ __forceinline__ void mma_tf32(float4& d,
    uint32_t a0, uint32_t a1, uint32_t a2, uint32_t a3,
    uint32_t b0, uint32_t b1)
{
    asm volatile(
        "mma.sync.aligned.m16n8k8.row.col.f32.tf32.tf32.f32 "
        "{%0,%1,%2,%3}, {%4,%5,%6,%7}, {%8,%9}, {%0,%1,%2,%3};\n"
        : "+f"(d.x), "+f"(d.y), "+f"(d.z), "+f"(d.w)
        : "r"(a0), "r"(a1), "r"(a2), "r"(a3), "r"(b0), "r"(b1));
}
__device__ __forceinline__ void mma_bf16(float4& d,
    uint32_t a0, uint32_t a1, uint32_t a2, uint32_t a3,
    uint32_t b0, uint32_t b1)
{
    asm volatile(
        "mma.sync.aligned.m16n8k16.row.col.f32.bf16.bf16.f32 "
        "{%0,%1,%2,%3}, {%4,%5,%6,%7}, {%8,%9}, {%0,%1,%2,%3};\n"
        : "+f"(d.x), "+f"(d.y), "+f"(d.z), "+f"(d.w)
        : "r"(a0), "r"(a1), "r"(a2), "r"(a3), "r"(b0), "r"(b1));
}

__device__ __forceinline__ void cp16(void* dst_smem, const void* src)
{
    uint32_t d = (uint32_t)__cvta_generic_to_shared(dst_smem);
    asm volatile("cp.async.cg.shared.global [%0], [%1], 16;" :: "r"(d), "l"(src));
}
#define CP_COMMIT() asm volatile("cp.async.commit_group;" ::: "memory")
#define CP_WAIT2()  asm volatile("cp.async.wait_group 2;"  ::: "memory")
#define CP_WAIT1()  asm volatile("cp.async.wait_group 1;"  ::: "memory")
#define CP_WAIT0()  asm volatile("cp.async.wait_group 0;"  ::: "memory")

// ---------------------------------------------------------------------------
// Kernel 1: all three projections in ONE launch (z = 0:K, 1:Q, 2:V).
// cp.async 4-stage pipeline, CTA 128x64, BK=16.
// z<2: 1x tf32.  z==2: 3x tf32.  Epilogue: bf16 hi/lo (V transposed).
// ---------------------------------------------------------------------------
#define NS 4
#define AK 20
#define BN 68
#define STG_F (128*AK + 16*BN)
#define PJ_SMEM (NS * STG_F * 4)   // 58368 bytes

__global__ __launch_bounds__(256) void proj_kernel(
    const float* __restrict__ Xk, const float* __restrict__ Xq, const float* __restrict__ Xv,
    const float* __restrict__ Wk, const float* __restrict__ Wq, const float* __restrict__ Wv)
{
    extern __shared__ float psm[];

    const int z = blockIdx.z;
    const float* X = (z == 0) ? Xk : (z == 1) ? Xq : Xv;
    const float* W = (z == 0) ? Wk : (z == 1) ? Wq : Wv;
    const bool split = (z == 2);

    const int tid  = threadIdx.x;
    const int lane = tid & 31;
    const int w    = tid >> 5;
    const int gid  = lane >> 2;
    const int tig  = lane & 3;
    const int wm   = w & 3;
    const int wn   = w >> 2;
    const int m0   = blockIdx.y * 128;
    const int n0   = blockIdx.x * 64;

    auto issue = [&](int s) {
        float* buf = psm + (s & 3) * STG_F;
        int k0 = s * 16;
#pragma unroll
        for (int l = 0; l < 2; l++) {
            int c   = tid + l * 256;
            int row = c >> 2;
            int kc  = (c & 3) * 4;
            cp16(buf + row * AK + kc, X + (size_t)(m0 + row) * DIN + k0 + kc);
        }
        {
            int row = tid >> 4;
            int nc  = (tid & 15) * 4;
            cp16(buf + 128 * AK + row * BN + nc,
                 W + (size_t)(k0 + row) * 512 + n0 + nc);
        }
    };

    float4 acc[2][4];
#pragma unroll
    for (int mt = 0; mt < 2; mt++)
#pragma unroll
        for (int nt = 0; nt < 4; nt++) acc[mt][nt] = make_float4(0.f,0.f,0.f,0.f);

    issue(0); CP_COMMIT();
    issue(1); CP_COMMIT();
    issue(2); CP_COMMIT();

#pragma unroll 1
    for (int s = 0; s < 32; s++) {
        CP_WAIT2();
        __syncthreads();

        float* Abuf = psm + (s & 3) * STG_F;
        float* Bbuf = Abuf + 128 * AK;
#pragma unroll
        for (int ks = 0; ks < 2; ks++) {
            int kb = ks * 8;
            float af[2][4];
#pragma unroll
            for (int mt = 0; mt < 2; mt++) {
                int m = wm * 32 + mt * 16;
                af[mt][0] = Abuf[(m + gid)     * AK + kb + tig];
                af[mt][1] = Abuf[(m + 8 + gid) * AK + kb + tig];
                af[mt][2] = Abuf[(m + gid)     * AK + kb + tig + 4];
                af[mt][3] = Abuf[(m + 8 + gid) * AK + kb + tig + 4];
            }
            if (!split) {
#pragma unroll
                for (int nt = 0; nt < 4; nt++) {
                    int n = wn * 32 + nt * 8;
                    uint32_t b0 = fbits(Bbuf[(kb + tig)     * BN + n + gid]);
                    uint32_t b1 = fbits(Bbuf[(kb + tig + 4) * BN + n + gid]);
#pragma unroll
                    for (int mt = 0; mt < 2; mt++)
                        mma_tf32(acc[mt][nt], fbits(af[mt][0]), fbits(af[mt][1]),
                                 fbits(af[mt][2]), fbits(af[mt][3]), b0, b1);
                }
            } else {
                uint32_t ah[2][4], al[2][4];
#pragma unroll
                for (int mt = 0; mt < 2; mt++)
#pragma unroll
                    for (int r = 0; r < 4; r++)
                        split_tf32(af[mt][r], ah[mt][r], al[mt][r]);
#pragma unroll
                for (int nt = 0; nt < 4; nt++) {
                    int n = wn * 32 + nt * 8;
                    uint32_t b0h, b0l, b1h, b1l;
                    split_tf32(Bbuf[(kb + tig)     * BN + n + gid], b0h, b0l);
                    split_tf32(Bbuf[(kb + tig + 4) * BN + n + gid], b1h, b1l);
#pragma unroll
                    for (int mt = 0; mt < 2; mt++) {
                        mma_tf32(acc[mt][nt], ah[mt][0], ah[mt][1], ah[mt][2], ah[mt][3], b0h, b1h);
                        mma_tf32(acc[mt][nt], al[mt][0], al[mt][1], al[mt][2], al[mt][3], b0h, b1h);
                        mma_tf32(acc[mt][nt], ah[mt][0], ah[mt][1], ah[mt][2], ah[mt][3], b0l, b1l);
                    }
                }
            }
        }

        __syncthreads();
        if (s + 3 < 32) issue(s + 3);
        CP_COMMIT();
    }

    // ---- Epilogue ----
    float* stage = psm;
    const int bb    = m0 >> 10;
    const int tbase = m0 & 1023;
#pragma unroll 1
    for (int pass = 0; pass < 4; pass++) {
        __syncthreads();
        if (wm == pass) {
#pragma unroll
            for (int mt = 0; mt < 2; mt++) {
#pragma unroll
                for (int nt = 0; nt < 4; nt++) {
                    int rl = mt * 16 + gid;
                    int cl = wn * 32 + nt * 8 + tig * 2;
                    float4 v = acc[mt][nt];
                    *(float2*)&stage[rl * 68 + cl]       = make_float2(v.x, v.y);
                    *(float2*)&stage[(rl + 8) * 68 + cl] = make_float2(v.z, v.w);
                }
            }
        }
        __syncthreads();
        int tp = tbase + pass * 32;
        if (z < 2) {
            int t = tid & 31;
            int h = (tid >> 5) & 7;
            uint32_t ph[4], pl[4];
#pragma unroll
            for (int j = 0; j < 4; j++)
                split_pack(stage[t * 68 + (2*j) * 8 + h],
                           stage[t * 68 + (2*j+1) * 8 + h], ph[j], pl[j]);
            size_t off = (size_t)(bb * NH + h) * TD + (size_t)(tp + t) * 64 + (n0 >> 3);
            if (z == 0) {
                *(uint4*)(g_Kh + off) = *(uint4*)ph;
                *(uint4*)(g_Kl + off) = *(uint4*)pl;
            } else {
                *(uint4*)(g_Qh + off) = *(uint4*)ph;
                *(uint4*)(g_Ql + off) = *(uint4*)pl;
            }
        } else {
            int dl = tid & 7;
            int h  = (tid >> 3) & 7;
            int tq = tid >> 6;
            uint32_t ph[4], pl[4];
#pragma unroll
            for (int j = 0; j < 4; j++) {
                int t0 = tq * 8 + 2 * j;
                split_pack(stage[t0 * 68 + dl * 8 + h],
                           stage[(t0 + 1) * 68 + dl * 8 + h], ph[j], pl[j]);
            }
            int d = (n0 >> 3) + dl;
            size_t off = (size_t)(bb * NH + h) * TD + (size_t)d * T_ + tp + tq * 8;
            *(uint4*)(g_Vth + off) = *(uint4*)ph;
            *(uint4*)(g_Vtl + off) = *(uint4*)pl;
        }
    }
}

// ---------------------------------------------------------------------------
// Kernel 2: flash attention, bf16 m16n8k16, 3xBF16 splitting,
// DOUBLE-BUFFERED cp.async K/V prefetch. Paired q-blocks (j, 7-j).
// ---------------------------------------------------------------------------
#define KSTR 72
#define KSTR32 36
#define STG_BF (4*64*KSTR)                  // bf16 per stage (Kh,Kl,Vh,Vl)
#define ATTN_SMEM_BYTES (2*STG_BF*2 + 2*8*16*KSTR*2 + 2*64*4)   // 111104

__global__ __launch_bounds__(256, 2) void attn_kernel(
    const int* __restrict__ key_seq, float* __restrict__ out)
{
    extern __shared__ char asmem[];
    __nv_bfloat16* KVbuf = (__nv_bfloat16*)asmem;            // 2 stages
    __nv_bfloat16* Ph    = KVbuf + 2 * STG_BF;
    __nv_bfloat16* Pl    = Ph + 8 * 16 * KSTR;
    int* smask           = (int*)(Pl + 8 * 16 * KSTR);       // [2][64]

    const int tid  = threadIdx.x;
    const int lane = tid & 31;
    const int w    = tid >> 5;
    const int gid  = lane >> 2;
    const int tig  = lane & 3;
    const int bh   = blockIdx.y;
    const int b    = bh >> 3;
    const int h    = bh & 7;
    const size_t base = (size_t)bh * TD;

    const __nv_bfloat16* gQh = g_Qh + base;
    const __nv_bfloat16* gQl = g_Ql + base;
    const __nv_bfloat16* gKh = g_Kh + base;
    const __nv_bfloat16* gKl = g_Kl + base;
    const __nv_bfloat16* gVh = g_Vth + base;
    const __nv_bfloat16* gVl = g_Vtl + base;
    const int* ksq = key_seq + b * T_;

    uint32_t* P32h = (uint32_t*)(Ph + w * 16 * KSTR);
    uint32_t* P32l = (uint32_t*)(Pl + w * 16 * KSTR);

    auto issue_kv = [&](int ti) {
        __nv_bfloat16* stg = KVbuf + (ti & 1) * STG_BF;
        int kb = ti * 64;
#pragma unroll
        for (int l = 0; l < 2; l++) {
            int f   = tid + l * 256;
            int r   = f >> 3;             // key (for K) / d (for V)
            int c   = (f & 7) * 8;
            cp16(stg + r * KSTR + c,                 gKh + (size_t)(kb + r) * 64 + c);
            cp16(stg + 64*KSTR + r * KSTR + c,       gKl + (size_t)(kb + r) * 64 + c);
            cp16(stg + 2*64*KSTR + r * KSTR + c,     gVh + (size_t)r * T_ + kb + c);
            cp16(stg + 3*64*KSTR + r * KSTR + c,     gVl + (size_t)r * T_ + kb + c);
        }
        if (tid < 16)
            cp16(smask + (ti & 1) * 64 + tid * 4, ksq + kb + tid * 4);
    };

#pragma unroll 1
    for (int pi = 0; pi < 2; pi++) {
        const int blk = pi ? (7 - blockIdx.x) : blockIdx.x;
        const int q0  = blk * 128;
        const int qlo = q0 + w * 16 + gid;
        const int qhi = qlo + 8;
        const int ntiles = (q0 + 128) >> 6;
        const int khi_w  = q0 + w * 16 + 16;

        uint32_t qh[4][4], ql[4][4];
#pragma unroll
        for (int kt = 0; kt < 4; kt++) {
            const __nv_bfloat16* rlo = gQh + (size_t)qlo * 64 + kt * 16;
            const __nv_bfloat16* rhi = gQh + (size_t)qhi * 64 + kt * 16;
            qh[kt][0] = *(const uint32_t*)(rlo + tig * 2);
            qh[kt][1] = *(const uint32_t*)(rhi + tig * 2);
            qh[kt][2] = *(const uint32_t*)(rlo + 8 + tig * 2);
            qh[kt][3] = *(const uint32_t*)(rhi + 8 + tig * 2);
            const __nv_bfloat16* slo = gQl + (size_t)qlo * 64 + kt * 16;
            const __nv_bfloat16* shi = gQl + (size_t)qhi * 64 + kt * 16;
            ql[kt][0] = *(const uint32_t*)(slo + tig * 2);
            ql[kt][1] = *(const uint32_t*)(shi + tig * 2);
            ql[kt][2] = *(const uint32_t*)(slo + 8 + tig * 2);
            ql[kt][3] = *(const uint32_t*)(shi + 8 + tig * 2);
        }

        float4 acc[8];
#pragma unroll
        for (int nt = 0; nt < 8; nt++) acc[nt] = make_float4(0.f,0.f,0.f,0.f);
        float m_lo = NEG_INF, m_hi = NEG_INF, l_lo = 0.f, l_hi = 0.f;

        issue_kv(0); CP_COMMIT();

#pragma unroll 1
        for (int ti = 0; ti < ntiles; ti++) {
            const int kb = ti * 64;
            const bool has_next = (ti + 1 < ntiles);
            if (has_next) issue_kv(ti + 1);
            CP_COMMIT();
            if (has_next) { CP_WAIT1(); } else { CP_WAIT0(); }
            __syncthreads();

            if (kb < khi_w) {
                uint32_t* K32h = (uint32_t*)(KVbuf + (ti & 1) * STG_BF);
                uint32_t* K32l = K32h + 64 * KSTR32;
                uint32_t* V32h = K32h + 2 * 64 * KSTR32;
                uint32_t* V32l = K32h + 3 * 64 * KSTR32;
                const int* sm_ = smask + (ti & 1) * 64;

                float4 s[8];
#pragma unroll
                for (int nt = 0; nt < 8; nt++) s[nt] = make_float4(0.f,0.f,0.f,0.f);
#pragma unroll
                for (int kt = 0; kt < 4; kt++) {
#pragma unroll
                    for (int nt = 0; nt < 8; nt++) {
                        int idx = (nt * 8 + gid) * KSTR32 + kt * 8 + tig;
                        uint32_t b0h = K32h[idx], b1h = K32h[idx + 4];
                        uint32_t b0l = K32l[idx], b1l = K32l[idx + 4];
                        mma_bf16(s[nt], qh[kt][0], qh[kt][1], qh[kt][2], qh[kt][3], b0h, b1h);
                        mma_bf16(s[nt], ql[kt][0], ql[kt][1], ql[kt][2], ql[kt][3], b0h, b1h);
                        mma_bf16(s[nt], qh[kt][0], qh[kt][1], qh[kt][2], qh[kt][3], b0l, b1l);
                    }
                }

                float mx_lo = NEG_INF, mx_hi = NEG_INF;
#pragma unroll
                for (int nt = 0; nt < 8; nt++) {
                    int ki  = kb + nt * 8 + tig * 2;
                    float b0f = (sm_[nt * 8 + tig * 2]     < 0) ? NEG_INF : 0.f;
                    float b1f = (sm_[nt * 8 + tig * 2 + 1] < 0) ? NEG_INF : 0.f;
                    s[nt].x = (ki     > qlo) ? NEG_INF : fmaf(s[nt].x, 0.125f, b0f);
                    s[nt].y = (ki + 1 > qlo) ? NEG_INF : fmaf(s[nt].y, 0.125f, b1f);
                    s[nt].z = (ki     > qhi) ? NEG_INF : fmaf(s[nt].z, 0.125f, b0f);
                    s[nt].w = (ki + 1 > qhi) ? NEG_INF : fmaf(s[nt].w, 0.125f, b1f);
                    mx_lo = fmaxf(mx_lo, fmaxf(s[nt].x, s[nt].y));
                    mx_hi = fmaxf(mx_hi, fmaxf(s[nt].z, s[nt].w));
                }
                mx_lo = fmaxf(mx_lo, __shfl_xor_sync(0xffffffffu, mx_lo, 1));
                mx_lo = fmaxf(mx_lo, __shfl_xor_sync(0xffffffffu, mx_lo, 2));
                mx_hi = fmaxf(mx_hi, __shfl_xor_sync(0xffffffffu, mx_hi, 1));
                mx_hi = fmaxf(mx_hi, __shfl_xor_sync(0xffffffffu, mx_hi, 2));

                float mn_lo = fmaxf(m_lo, mx_lo);
                float mn_hi = fmaxf(m_hi, mx_hi);
                float al_lo = __expf(m_lo - mn_lo);
                float al_hi = __expf(m_hi - mn_hi);

                float sum_lo = 0.f, sum_hi = 0.f;
#pragma unroll
                for (int nt = 0; nt < 8; nt++) {
                    s[nt].x = __expf(s[nt].x - mn_lo);
                    s[nt].y = __expf(s[nt].y - mn_lo);
                    s[nt].z = __expf(s[nt].z - mn_hi);
                    s[nt].w = __expf(s[nt].w - mn_hi);
                    sum_lo += s[nt].x + s[nt].y;
                    sum_hi += s[nt].z + s[nt].w;
                }
                sum_lo += __shfl_xor_sync(0xffffffffu, sum_lo, 1);
                sum_lo += __shfl_xor_sync(0xffffffffu, sum_lo, 2);
                sum_hi += __shfl_xor_sync(0xffffffffu, sum_hi, 1);
                sum_hi += __shfl_xor_sync(0xffffffffu, sum_hi, 2);

                l_lo = l_lo * al_lo + sum_lo;  m_lo = mn_lo;
                l_hi = l_hi * al_hi + sum_hi;  m_hi = mn_hi;

#pragma unroll
                for (int nt = 0; nt < 8; nt++) {
                    acc[nt].x *= al_lo;  acc[nt].y *= al_lo;
                    acc[nt].z *= al_hi;  acc[nt].w *= al_hi;
                }

#pragma unroll
                for (int nt = 0; nt < 8; nt++) {
                    uint32_t phx, plx, phz, plz;
                    split_pack(s[nt].x, s[nt].y, phx, plx);
                    split_pack(s[nt].z, s[nt].w, phz, plz);
                    int c = nt * 4 + tig;
                    P32h[gid * KSTR32 + c]       = phx;
                    P32l[gid * KSTR32 + c]       = plx;
                    P32h[(gid + 8) * KSTR32 + c] = phz;
                    P32l[(gid + 8) * KSTR32 + c] = plz;
                }
                __syncwarp();

#pragma unroll
                for (int kt = 0; kt < 4; kt++) {
                    uint32_t pah[4], pal[4];
                    pah[0] = P32h[gid * KSTR32 + kt * 8 + tig];
                    pah[1] = P32h[(gid + 8) * KSTR32 + kt * 8 + tig];
                    pah[2] = P32h[gid * KSTR32 + kt * 8 + tig + 4];
                    pah[3] = P32h[(gid + 8) * KSTR32 + kt * 8 + tig + 4];
                    pal[0] = P32l[gid * KSTR32 + kt * 8 + tig];
                    pal[1] = P32l[(gid + 8) * KSTR32 + kt * 8 + tig];
                    pal[2] = P32l[gid * KSTR32 + kt * 8 + tig + 4];
                    pal[3] = P32l[(gid + 8) * KSTR32 + kt * 8 + tig + 4];
#pragma unroll
                    for (int nt = 0; nt < 8; nt++) {
                        int idx = (nt * 8 + gid) * KSTR32 + kt * 8 + tig;
                        uint32_t b0h = V32h[idx], b1h = V32h[idx + 4];
                        uint32_t b0l = V32l[idx], b1l = V32l[idx + 4];
                        mma_bf16(acc[nt], pah[0], pah[1], pah[2], pah[3], b0h, b1h);
                        mma_bf16(acc[nt], pal[0], pal[1], pal[2], pal[3], b0h, b1h);
                        mma_bf16(acc[nt], pah[0], pah[1], pah[2], pah[3], b0l, b1l);
                    }
                }
            }

            __syncthreads();   // all warps done with stage ti before it's reused
        }

        float il_lo = 1.f / l_lo;
        float il_hi = 1.f / l_hi;
#pragma unroll
        for (int nt = 0; nt < 8; nt++) {
            int col = h * DH + nt * 8 + tig * 2;
            *(float2*)(out + (size_t)(b * T_ + qlo) * (NH * DH) + col) =
                make_float2(acc[nt].x * il_lo, acc[nt].y * il_lo);
            *(float2*)(out + (size_t)(b * T_ + qhi) * (NH * DH) + col) =
                make_float2(acc[nt].z * il_hi, acc[nt].w * il_hi);
        }
    }
}

// ---------------------------------------------------------------------------
extern "C" void kernel_launch(void* const* d_in, const int* in_sizes, int n_in,
                              void* d_out, int out_size)
{
    const float* keys    = (const float*)d_in[0];
    const float* queries = (const float*)d_in[1];
    const float* values  = (const float*)d_in[2];
    const float* Wk      = (const float*)d_in[3];
    const float* Wq      = (const float*)d_in[4];
    const float* Wv      = (const float*)d_in[5];
    const int*   key_seq = (const int*)d_in[6];
    float* out = (float*)d_out;

    cudaFuncSetAttribute(proj_kernel,
                         cudaFuncAttributeMaxDynamicSharedMemorySize, PJ_SMEM);
    dim3 g1(512 / 64, (B_ * T_) / 128, 3);
    proj_kernel<<<g1, 256, PJ_SMEM>>>(keys, queries, values, Wk, Wq, Wv);

    cudaFuncSetAttribute(attn_kernel,
                         cudaFuncAttributeMaxDynamicSharedMemorySize, ATTN_SMEM_BYTES);
    dim3 g2(4, BH);
    attn_kernel<<<g2, 256, ATTN_SMEM_BYTES>>>(key_seq, out);
}

// round 12
// speedup vs baseline: 1.3710x; 1.0435x over previous
#include <cuda_runtime.h>
#include <cuda_bf16.h>
#include <cstdint>

using std::uint32_t;

#define B_ 8
#define T_ 1024
#define DIN 512
#define DH 64
#define NH 8
#define BH (B_*NH)
#define TD (T_*DH)

#define NEG_INF (-1e30f)

// Scratch (bf16 hi/lo splits of fp32-accurate projections):
//  K,Q: [bh][t][d].  V: TRANSPOSED [bh][d][t].
__device__ __nv_bfloat16 g_Kh [BH * TD];
__device__ __nv_bfloat16 g_Kl [BH * TD];
__device__ __nv_bfloat16 g_Qh [BH * TD];
__device__ __nv_bfloat16 g_Ql [BH * TD];
__device__ __nv_bfloat16 g_Vth[BH * TD];
__device__ __nv_bfloat16 g_Vtl[BH * TD];

__device__ __forceinline__ uint32_t fbits(float x) { return __float_as_uint(x); }

__device__ __forceinline__ void bf_split(float x, __nv_bfloat16& h, __nv_bfloat16& l)
{
    h = __float2bfloat16(x);
    l = __float2bfloat16(x - __bfloat162float(h));
}
__device__ __forceinline__ uint32_t pack_bf2(__nv_bfloat16 a, __nv_bfloat16 b)
{
    __nv_bfloat162 t; t.x = a; t.y = b;
    return *reinterpret_cast<uint32_t*>(&t);
}
__device__ __forceinline__ void split_pack(float x, float y, uint32_t& ph, uint32_t& pl)
{
    __nv_bfloat16 hx, lx, hy, ly;
    bf_split(x, hx, lx);
    bf_split(y, hy, ly);
    ph = pack_bf2(hx, hy);
    pl = pack_bf2(lx, ly);
}

__device__ __forceinline__ void mma_tf32(float4& d,
    uint32_t a0, uint32_t a1, uint32_t a2, uint32_t a3,
    uint32_t b0, uint32_t b1)
{
    asm volatile(
        "mma.sync.aligned.m16n8k8.row.col.f32.tf32.tf32.f32 "
        "{%0,%1,%2,%3}, {%4,%5,%6,%7}, {%8,%9}, {%0,%1,%2,%3};\n"
        : "+f"(d.x), "+f"(d.y), "+f"(d.z), "+f"(d.w)
        : "r"(a0), "r"(a1), "r"(a2), "r"(a3), "r"(b0), "r"(b1));
}
__device__ __forceinline__ void mma_bf16(float4& d,
    uint32_t a0, uint32_t a1, uint32_t a2, uint32_t a3,
    uint32_t b0, uint32_t b1)
{
    asm volatile(
        "mma.sync.aligned.m16n8k16.row.col.f32.bf16.bf16.f32 "
        "{%0,%1,%2,%3}, {%4,%5,%6,%7}, {%8,%9}, {%0,%1,%2,%3};\n"
        : "+f"(d.x), "+f"(d.y), "+f"(d.z), "+f"(d.w)
        : "r"(a0), "r"(a1), "r"(a2), "r"(a3), "r"(b0), "r"(b1));
}

__device__ __forceinline__ void cp16(void* dst_smem, const void* src)
{
    uint32_t d = (uint32_t)__cvta_generic_to_shared(dst_smem);
    asm volatile("cp.async.cg.shared.global [%0], [%1], 16;" :: "r"(d), "l"(src));
}
#define CP_COMMIT() asm volatile("cp.async.commit_group;" ::: "memory")
#define CP_WAIT2()  asm volatile("cp.async.wait_group 2;"  ::: "memory")
#define CP_WAIT1()  asm volatile("cp.async.wait_group 1;"  ::: "memory")
#define CP_WAIT0()  asm volatile("cp.async.wait_group 0;"  ::: "memory")

// ---------------------------------------------------------------------------
// Kernel 1: all three projections in ONE launch (z = 0:K, 1:Q, 2:V).
// cp.async 4-stage pipeline, CTA 128x64, BK=16.
// z<2: 1x tf32 (m16n8k8).  z==2: 3x BF16 (m16n8k16, in-register hi/lo split
// from the same fp32 smem stages — halves V's MMA issue count).
// Epilogue: bf16 hi/lo; K/Q -> [bh][t][d], V -> transposed [bh][d][t].
// ---------------------------------------------------------------------------
#define NS 4
#define AK 20
#define BN 68
#define STG_F (128*AK + 16*BN)
#define PJ_SMEM (NS * STG_F * 4)   // 58368 bytes

__global__ __launch_bounds__(256) void proj_kernel(
    const float* __restrict__ Xk, const float* __restrict__ Xq, const float* __restrict__ Xv,
    const float* __restrict__ Wk, const float* __restrict__ Wq, const float* __restrict__ Wv)
{
    extern __shared__ float psm[];

    const int z = blockIdx.z;
    const float* X = (z == 0) ? Xk : (z == 1) ? Xq : Xv;
    const float* W = (z == 0) ? Wk : (z == 1) ? Wq : Wv;
    const bool split = (z == 2);

    const int tid  = threadIdx.x;
    const int lane = tid & 31;
    const int w    = tid >> 5;
    const int gid  = lane >> 2;
    const int tig  = lane & 3;
    const int wm   = w & 3;
    const int wn   = w >> 2;
    const int m0   = blockIdx.y * 128;
    const int n0   = blockIdx.x * 64;

    auto issue = [&](int s) {
        float* buf = psm + (s & 3) * STG_F;
        int k0 = s * 16;
#pragma unroll
        for (int l = 0; l < 2; l++) {
            int c   = tid + l * 256;
            int row = c >> 2;
            int kc  = (c & 3) * 4;
            cp16(buf + row * AK + kc, X + (size_t)(m0 + row) * DIN + k0 + kc);
        }
        {
            int row = tid >> 4;
            int nc  = (tid & 15) * 4;
            cp16(buf + 128 * AK + row * BN + nc,
                 W + (size_t)(k0 + row) * 512 + n0 + nc);
        }
    };

    float4 acc[2][4];
#pragma unroll
    for (int mt = 0; mt < 2; mt++)
#pragma unroll
        for (int nt = 0; nt < 4; nt++) acc[mt][nt] = make_float4(0.f,0.f,0.f,0.f);

    issue(0); CP_COMMIT();
    issue(1); CP_COMMIT();
    issue(2); CP_COMMIT();

#pragma unroll 1
    for (int s = 0; s < 32; s++) {
        CP_WAIT2();
        __syncthreads();

        float* Abuf = psm + (s & 3) * STG_F;
        float* Bbuf = Abuf + 128 * AK;

        if (!split) {
#pragma unroll
            for (int ks = 0; ks < 2; ks++) {
                int kb = ks * 8;
                uint32_t a[2][4];
#pragma unroll
                for (int mt = 0; mt < 2; mt++) {
                    int m = wm * 32 + mt * 16;
                    a[mt][0] = fbits(Abuf[(m + gid)     * AK + kb + tig]);
                    a[mt][1] = fbits(Abuf[(m + 8 + gid) * AK + kb + tig]);
                    a[mt][2] = fbits(Abuf[(m + gid)     * AK + kb + tig + 4]);
                    a[mt][3] = fbits(Abuf[(m + 8 + gid) * AK + kb + tig + 4]);
                }
#pragma unroll
                for (int nt = 0; nt < 4; nt++) {
                    int n = wn * 32 + nt * 8;
                    uint32_t b0 = fbits(Bbuf[(kb + tig)     * BN + n + gid]);
                    uint32_t b1 = fbits(Bbuf[(kb + tig + 4) * BN + n + gid]);
#pragma unroll
                    for (int mt = 0; mt < 2; mt++)
                        mma_tf32(acc[mt][nt], a[mt][0], a[mt][1], a[mt][2], a[mt][3], b0, b1);
                }
            }
        } else {
            // ---- V path: one k16 step, 3xBF16 (Ah*Bh + Al*Bh + Ah*Bl) ----
            uint32_t ah[2][4], al[2][4];
#pragma unroll
            for (int mt = 0; mt < 2; mt++) {
                int m = wm * 32 + mt * 16;
                const float* r0 = Abuf + (m + gid)     * AK;
                const float* r1 = Abuf + (m + 8 + gid) * AK;
                split_pack(r0[2*tig],     r0[2*tig + 1], ah[mt][0], al[mt][0]);
                split_pack(r1[2*tig],     r1[2*tig + 1], ah[mt][1], al[mt][1]);
                split_pack(r0[2*tig + 8], r0[2*tig + 9], ah[mt][2], al[mt][2]);
                split_pack(r1[2*tig + 8], r1[2*tig + 9], ah[mt][3], al[mt][3]);
            }
#pragma unroll
            for (int nt = 0; nt < 4; nt++) {
                int n = wn * 32 + nt * 8 + gid;
                uint32_t b0h, b0l, b1h, b1l;
                split_pack(Bbuf[(2*tig)     * BN + n], Bbuf[(2*tig + 1) * BN + n], b0h, b0l);
                split_pack(Bbuf[(2*tig + 8) * BN + n], Bbuf[(2*tig + 9) * BN + n], b1h, b1l);
#pragma unroll
                for (int mt = 0; mt < 2; mt++) {
                    mma_bf16(acc[mt][nt], ah[mt][0], ah[mt][1], ah[mt][2], ah[mt][3], b0h, b1h);
                    mma_bf16(acc[mt][nt], al[mt][0], al[mt][1], al[mt][2], al[mt][3], b0h, b1h);
                    mma_bf16(acc[mt][nt], ah[mt][0], ah[mt][1], ah[mt][2], ah[mt][3], b0l, b1l);
                }
            }
        }

        __syncthreads();
        if (s + 3 < 32) issue(s + 3);
        CP_COMMIT();
    }

    // ---- Epilogue ----
    float* stage = psm;
    const int bb    = m0 >> 10;
    const int tbase = m0 & 1023;
#pragma unroll 1
    for (int pass = 0; pass < 4; pass++) {
        __syncthreads();
        if (wm == pass) {
#pragma unroll
            for (int mt = 0; mt < 2; mt++) {
#pragma unroll
                for (int nt = 0; nt < 4; nt++) {
                    int rl = mt * 16 + gid;
                    int cl = wn * 32 + nt * 8 + tig * 2;
                    float4 v = acc[mt][nt];
                    *(float2*)&stage[rl * 68 + cl]       = make_float2(v.x, v.y);
                    *(float2*)&stage[(rl + 8) * 68 + cl] = make_float2(v.z, v.w);
                }
            }
        }
        __syncthreads();
        int tp = tbase + pass * 32;
        if (z < 2) {
            int t = tid & 31;
            int h = (tid >> 5) & 7;
            uint32_t ph[4], pl[4];
#pragma unroll
            for (int j = 0; j < 4; j++)
                split_pack(stage[t * 68 + (2*j) * 8 + h],
                           stage[t * 68 + (2*j+1) * 8 + h], ph[j], pl[j]);
            size_t off = (size_t)(bb * NH + h) * TD + (size_t)(tp + t) * 64 + (n0 >> 3);
            if (z == 0) {
                *(uint4*)(g_Kh + off) = *(uint4*)ph;
                *(uint4*)(g_Kl + off) = *(uint4*)pl;
            } else {
                *(uint4*)(g_Qh + off) = *(uint4*)ph;
                *(uint4*)(g_Ql + off) = *(uint4*)pl;
            }
        } else {
            int dl = tid & 7;
            int h  = (tid >> 3) & 7;
            int tq = tid >> 6;
            uint32_t ph[4], pl[4];
#pragma unroll
            for (int j = 0; j < 4; j++) {
                int t0 = tq * 8 + 2 * j;
                split_pack(stage[t0 * 68 + dl * 8 + h],
                           stage[(t0 + 1) * 68 + dl * 8 + h], ph[j], pl[j]);
            }
            int d = (n0 >> 3) + dl;
            size_t off = (size_t)(bb * NH + h) * TD + (size_t)d * T_ + tp + tq * 8;
            *(uint4*)(g_Vth + off) = *(uint4*)ph;
            *(uint4*)(g_Vtl + off) = *(uint4*)pl;
        }
    }
}

// ---------------------------------------------------------------------------
// Kernel 2: flash attention (R11 — best measured). bf16 m16n8k16, 3xBF16,
// double-buffered cp.async K/V prefetch, paired q-blocks (j, 7-j).
// ---------------------------------------------------------------------------
#define KSTR 72
#define KSTR32 36
#define STG_BF (4*64*KSTR)
#define ATTN_SMEM_BYTES (2*STG_BF*2 + 2*8*16*KSTR*2 + 2*64*4)   // 111104

__global__ __launch_bounds__(256, 2) void attn_kernel(
    const int* __restrict__ key_seq, float* __restrict__ out)
{
    extern __shared__ char asmem[];
    __nv_bfloat16* KVbuf = (__nv_bfloat16*)asmem;
    __nv_bfloat16* Ph    = KVbuf + 2 * STG_BF;
    __nv_bfloat16* Pl    = Ph + 8 * 16 * KSTR;
    int* smask           = (int*)(Pl + 8 * 16 * KSTR);

    const int tid  = threadIdx.x;
    const int lane = tid & 31;
    const int w    = tid >> 5;
    const int gid  = lane >> 2;
    const int tig  = lane & 3;
    const int bh   = blockIdx.y;
    const int b    = bh >> 3;
    const int h    = bh & 7;
    const size_t base = (size_t)bh * TD;

    const __nv_bfloat16* gQh = g_Qh + base;
    const __nv_bfloat16* gQl = g_Ql + base;
    const __nv_bfloat16* gKh = g_Kh + base;
    const __nv_bfloat16* gKl = g_Kl + base;
    const __nv_bfloat16* gVh = g_Vth + base;
    const __nv_bfloat16* gVl = g_Vtl + base;
    const int* ksq = key_seq + b * T_;

    uint32_t* P32h = (uint32_t*)(Ph + w * 16 * KSTR);
    uint32_t* P32l = (uint32_t*)(Pl + w * 16 * KSTR);

    auto issue_kv = [&](int ti) {
        __nv_bfloat16* stg = KVbuf + (ti & 1) * STG_BF;
        int kb = ti * 64;
#pragma unroll
        for (int l = 0; l < 2; l++) {
            int f   = tid + l * 256;
            int r   = f >> 3;
            int c   = (f & 7) * 8;
            cp16(stg + r * KSTR + c,             gKh + (size_t)(kb + r) * 64 + c);
            cp16(stg + 64*KSTR + r * KSTR + c,   gKl + (size_t)(kb + r) * 64 + c);
            cp16(stg + 2*64*KSTR + r * KSTR + c, gVh + (size_t)r * T_ + kb + c);
            cp16(stg + 3*64*KSTR + r * KSTR + c, gVl + (size_t)r * T_ + kb + c);
        }
        if (tid < 16)
            cp16(smask + (ti & 1) * 64 + tid * 4, ksq + kb + tid * 4);
    };

#pragma unroll 1
    for (int pi = 0; pi < 2; pi++) {
        const int blk = pi ? (7 - blockIdx.x) : blockIdx.x;
        const int q0  = blk * 128;
        const int qlo = q0 + w * 16 + gid;
        const int qhi = qlo + 8;
        const int ntiles = (q0 + 128) >> 6;
        const int khi_w  = q0 + w * 16 + 16;

        uint32_t qh[4][4], ql[4][4];
#pragma unroll
        for (int kt = 0; kt < 4; kt++) {
            const __nv_bfloat16* rlo = gQh + (size_t)qlo * 64 + kt * 16;
            const __nv_bfloat16* rhi = gQh + (size_t)qhi * 64 + kt * 16;
            qh[kt][0] = *(const uint32_t*)(rlo + tig * 2);
            qh[kt][1] = *(const uint32_t*)(rhi + tig * 2);
            qh[kt][2] = *(const uint32_t*)(rlo + 8 + tig * 2);
            qh[kt][3] = *(const uint32_t*)(rhi + 8 + tig * 2);
            const __nv_bfloat16* slo = gQl + (size_t)qlo * 64 + kt * 16;
            const __nv_bfloat16* shi = gQl + (size_t)qhi * 64 + kt * 16;
            ql[kt][0] = *(const uint32_t*)(slo + tig * 2);
            ql[kt][1] = *(const uint32_t*)(shi + tig * 2);
            ql[kt][2] = *(const uint32_t*)(slo + 8 + tig * 2);
            ql[kt][3] = *(const uint32_t*)(shi + 8 + tig * 2);
        }

        float4 acc[8];
#pragma unroll
        for (int nt = 0; nt < 8; nt++) acc[nt] = make_float4(0.f,0.f,0.f,0.f);
        float m_lo = NEG_INF, m_hi = NEG_INF, l_lo = 0.f, l_hi = 0.f;

        issue_kv(0); CP_COMMIT();

#pragma unroll 1
        for (int ti = 0; ti < ntiles; ti++) {
            const int kb = ti * 64;
            const bool has_next = (ti + 1 < ntiles);
            if (has_next) issue_kv(ti + 1);
            CP_COMMIT();
            if (has_next) { CP_WAIT1(); } else { CP_WAIT0(); }
            __syncthreads();

            if (kb < khi_w) {
                uint32_t* K32h = (uint32_t*)(KVbuf + (ti & 1) * STG_BF);
                uint32_t* K32l = K32h + 64 * KSTR32;
                uint32_t* V32h = K32h + 2 * 64 * KSTR32;
                uint32_t* V32l = K32h + 3 * 64 * KSTR32;
                const int* sm_ = smask + (ti & 1) * 64;

                float4 s[8];
#pragma unroll
                for (int nt = 0; nt < 8; nt++) s[nt] = make_float4(0.f,0.f,0.f,0.f);
#pragma unroll
                for (int kt = 0; kt < 4; kt++) {
#pragma unroll
                    for (int nt = 0; nt < 8; nt++) {
                        int idx = (nt * 8 + gid) * KSTR32 + kt * 8 + tig;
                        uint32_t b0h = K32h[idx], b1h = K32h[idx + 4];
                        uint32_t b0l = K32l[idx], b1l = K32l[idx + 4];
                        mma_bf16(s[nt], qh[kt][0], qh[kt][1], qh[kt][2], qh[kt][3], b0h, b1h);
                        mma_bf16(s[nt], ql[kt][0], ql[kt][1], ql[kt][2], ql[kt][3], b0h, b1h);
                        mma_bf16(s[nt], qh[kt][0], qh[kt][1], qh[kt][2], qh[kt][3], b0l, b1l);
                    }
                }

                float mx_lo = NEG_INF, mx_hi = NEG_INF;
#pragma unroll
                for (int nt = 0; nt < 8; nt++) {
                    int ki  = kb + nt * 8 + tig * 2;
                    float b0f = (sm_[nt * 8 + tig * 2]     < 0) ? NEG_INF : 0.f;
                    float b1f = (sm_[nt * 8 + tig * 2 + 1] < 0) ? NEG_INF : 0.f;
                    s[nt].x = (ki     > qlo) ? NEG_INF : fmaf(s[nt].x, 0.125f, b0f);
                    s[nt].y = (ki + 1 > qlo) ? NEG_INF : fmaf(s[nt].y, 0.125f, b1f);
                    s[nt].z = (ki     > qhi) ? NEG_INF : fmaf(s[nt].z, 0.125f, b0f);
                    s[nt].w = (ki + 1 > qhi) ? NEG_INF : fmaf(s[nt].w, 0.125f, b1f);
                    mx_lo = fmaxf(mx_lo, fmaxf(s[nt].x, s[nt].y));
                    mx_hi = fmaxf(mx_hi, fmaxf(s[nt].z, s[nt].w));
                }
                mx_lo = fmaxf(mx_lo, __shfl_xor_sync(0xffffffffu, mx_lo, 1));
                mx_lo = fmaxf(mx_lo, __shfl_xor_sync(0xffffffffu, mx_lo, 2));
                mx_hi = fmaxf(mx_hi, __shfl_xor_sync(0xffffffffu, mx_hi, 1));
                mx_hi = fmaxf(mx_hi, __shfl_xor_sync(0xffffffffu, mx_hi, 2));

                float mn_lo = fmaxf(m_lo, mx_lo);
                float mn_hi = fmaxf(m_hi, mx_hi);
                float al_lo = __expf(m_lo - mn_lo);
                float al_hi = __expf(m_hi - mn_hi);

                float sum_lo = 0.f, sum_hi = 0.f;
#pragma unroll
                for (int nt = 0; nt < 8; nt++) {
                    s[nt].x = __expf(s[nt].x - mn_lo);
                    s[nt].y = __expf(s[nt].y - mn_lo);
                    s[nt].z = __expf(s[nt].z - mn_hi);
                    s[nt].w = __expf(s[nt].w - mn_hi);
                    sum_lo += s[nt].x + s[nt].y;
                    sum_hi += s[nt].z + s[nt].w;
                }
                sum_lo += __shfl_xor_sync(0xffffffffu, sum_lo, 1);
                sum_lo += __shfl_xor_sync(0xffffffffu, sum_lo, 2);
                sum_hi += __shfl_xor_sync(0xffffffffu, sum_hi, 1);
                sum_hi += __shfl_xor_sync(0xffffffffu, sum_hi, 2);

                l_lo = l_lo * al_lo + sum_lo;  m_lo = mn_lo;
                l_hi = l_hi * al_hi + sum_hi;  m_hi = mn_hi;

#pragma unroll
                for (int nt = 0; nt < 8; nt++) {
                    acc[nt].x *= al_lo;  acc[nt].y *= al_lo;
                    acc[nt].z *= al_hi;  acc[nt].w *= al_hi;
                }

#pragma unroll
                for (int nt = 0; nt < 8; nt++) {
                    uint32_t phx, plx, phz, plz;
                    split_pack(s[nt].x, s[nt].y, phx, plx);
                    split_pack(s[nt].z, s[nt].w, phz, plz);
                    int c = nt * 4 + tig;
                    P32h[gid * KSTR32 + c]       = phx;
                    P32l[gid * KSTR32 + c]       = plx;
                    P32h[(gid + 8) * KSTR32 + c] = phz;
                    P32l[(gid + 8) * KSTR32 + c] = plz;
                }
                __syncwarp();

#pragma unroll
                for (int kt = 0; kt < 4; kt++) {
                    uint32_t pah[4], pal[4];
                    pah[0] = P32h[gid * KSTR32 + kt * 8 + tig];
                    pah[1] = P32h[(gid + 8) * KSTR32 + kt * 8 + tig];
                    pah[2] = P32h[gid * KSTR32 + kt * 8 + tig + 4];
                    pah[3] = P32h[(gid + 8) * KSTR32 + kt * 8 + tig + 4];
                    pal[0] = P32l[gid * KSTR32 + kt * 8 + tig];
                    pal[1] = P32l[(gid + 8) * KSTR32 + kt * 8 + tig];
                    pal[2] = P32l[gid * KSTR32 + kt * 8 + tig + 4];
                    pal[3] = P32l[(gid + 8) * KSTR32 + kt * 8 + tig + 4];
#pragma unroll
                    for (int nt = 0; nt < 8; nt++) {
                        int idx = (nt * 8 + gid) * KSTR32 + kt * 8 + tig;
                        uint32_t b0h = V32h[idx], b1h = V32h[idx + 4];
                        uint32_t b0l = V32l[idx], b1l = V32l[idx + 4];
                        mma_bf16(acc[nt], pah[0], pah[1], pah[2], pah[3], b0h, b1h);
                        mma_bf16(acc[nt], pal[0], pal[1], pal[2], pal[3], b0h, b1h);
                        mma_bf16(acc[nt], pah[0], pah[1], pah[2], pah[3], b0l, b1l);
                    }
                }
            }

            __syncthreads();
        }

        float il_lo = 1.f / l_lo;
        float il_hi = 1.f / l_hi;
#pragma unroll
        for (int nt = 0; nt < 8; nt++) {
            int col = h * DH + nt * 8 + tig * 2;
            *(float2*)(out + (size_t)(b * T_ + qlo) * (NH * DH) + col) =
                make_float2(acc[nt].x * il_lo, acc[nt].y * il_lo);
            *(float2*)(out + (size_t)(b * T_ + qhi) * (NH * DH) + col) =
                make_float2(acc[nt].z * il_hi, acc[nt].w * il_hi);
        }
    }
}

// ---------------------------------------------------------------------------
extern "C" void kernel_launch(void* const* d_in, const int* in_sizes, int n_in,
                              void* d_out, int out_size)
{
    const float* keys    = (const float*)d_in[0];
    const float* queries = (const float*)d_in[1];
    const float* values  = (const float*)d_in[2];
    const float* Wk      = (const float*)d_in[3];
    const float* Wq      = (const float*)d_in[4];
    const float* Wv      = (const float*)d_in[5];
    const int*   key_seq = (const int*)d_in[6];
    float* out = (float*)d_out;

    cudaFuncSetAttribute(proj_kernel,
                         cudaFuncAttributeMaxDynamicSharedMemorySize, PJ_SMEM);
    dim3 g1(512 / 64, (B_ * T_) / 128, 3);
    proj_kernel<<<g1, 256, PJ_SMEM>>>(keys, queries, values, Wk, Wq, Wv);

    cudaFuncSetAttribute(attn_kernel,
                         cudaFuncAttributeMaxDynamicSharedMemorySize, ATTN_SMEM_BYTES);
    dim3 g2(4, BH);
    attn_kernel<<<g2, 256, ATTN_SMEM_BYTES>>>(key_seq, out);
}